// round 6
// baseline (speedup 1.0000x reference)
#include <cuda_runtime.h>
#include <cuda_bf16.h>
#include <cstdint>

// Problem constants
#define BB 2
#define SS 8192
#define DD 1024
#define HH 16
#define DK 64
#define WW 128
#define NB (SS / 128)

typedef __nv_bfloat16 bf16;

// ---------------------------------------------------------------------------
// Scratch (device globals)
// ---------------------------------------------------------------------------
__device__ bf16 g_qhi[(size_t)BB * HH * SS * DK];
__device__ bf16 g_qlo[(size_t)BB * HH * SS * DK];
__device__ bf16 g_khi[(size_t)BB * HH * SS * DK];
__device__ bf16 g_klo[(size_t)BB * HH * SS * DK];
__device__ bf16 g_vhi[(size_t)BB * HH * SS * DK];
__device__ bf16 g_vlo[(size_t)BB * HH * SS * DK];
__device__ bf16 g_ahi[(size_t)16384 * 1024];
__device__ bf16 g_alo[(size_t)16384 * 1024];
__device__ bf16 g_wqkv_hi[(size_t)3072 * 1024];
__device__ bf16 g_wqkv_lo[(size_t)3072 * 1024];
__device__ bf16 g_wo_hi[(size_t)1024 * 1024];
__device__ bf16 g_wo_lo[(size_t)1024 * 1024];

// ---------------------------------------------------------------------------
// Helpers
// ---------------------------------------------------------------------------
__device__ __forceinline__ uint32_t smem_u32(const void* p) {
    uint32_t a;
    asm("{ .reg .u64 t; cvta.to.shared.u64 t, %1; cvt.u32.u64 %0, t; }"
        : "=r"(a) : "l"(p));
    return a;
}
__device__ __forceinline__ void cpa16(uint32_t s, const void* g) {
    asm volatile("cp.async.cg.shared.global [%0], [%1], 16;" :: "r"(s), "l"(g));
}
__device__ __forceinline__ void ldx4(uint32_t* r, uint32_t addr) {
    asm volatile("ldmatrix.sync.aligned.m8n8.x4.shared.b16 {%0,%1,%2,%3}, [%4];"
                 : "=r"(r[0]), "=r"(r[1]), "=r"(r[2]), "=r"(r[3]) : "r"(addr));
}
__device__ __forceinline__ void ldx4t(uint32_t* r, uint32_t addr) {
    asm volatile("ldmatrix.sync.aligned.m8n8.x4.trans.shared.b16 {%0,%1,%2,%3}, [%4];"
                 : "=r"(r[0]), "=r"(r[1]), "=r"(r[2]), "=r"(r[3]) : "r"(addr));
}
__device__ __forceinline__ void mma16816(float* c, const uint32_t* a,
                                         const uint32_t* b) {
    asm volatile(
        "mma.sync.aligned.m16n8k16.row.col.f32.bf16.bf16.f32 "
        "{%0,%1,%2,%3}, {%4,%5,%6,%7}, {%8,%9}, {%0,%1,%2,%3};"
        : "+f"(c[0]), "+f"(c[1]), "+f"(c[2]), "+f"(c[3])
        : "r"(a[0]), "r"(a[1]), "r"(a[2]), "r"(a[3]), "r"(b[0]), "r"(b[1]));
}
__device__ __forceinline__ uint32_t packbf2(bf16 a, bf16 b) {
    __nv_bfloat162 t;
    t.x = a; t.y = b;
    return *reinterpret_cast<uint32_t*>(&t);
}
__device__ __forceinline__ void split2(float a, float b, uint32_t& hi, uint32_t& lo) {
    bf16 ha = __float2bfloat16(a), hb = __float2bfloat16(b);
    bf16 la = __float2bfloat16(a - __bfloat162float(ha));
    bf16 lb = __float2bfloat16(b - __bfloat162float(hb));
    hi = packbf2(ha, hb);
    lo = packbf2(la, lb);
}

// ---------------------------------------------------------------------------
// Elementwise fp32 -> bf16 hi/lo split (for x)
// ---------------------------------------------------------------------------
__global__ __launch_bounds__(256)
void convsplit(const float* __restrict__ in, bf16* __restrict__ hi,
               bf16* __restrict__ lo) {
    size_t i = ((size_t)blockIdx.x * 256 + threadIdx.x) * 8;
    float4 a = *(const float4*)(in + i);
    float4 b = *(const float4*)(in + i + 4);
    float v[8] = {a.x, a.y, a.z, a.w, b.x, b.y, b.z, b.w};
    bf16 h[8], l[8];
#pragma unroll
    for (int j = 0; j < 8; j++) {
        h[j] = __float2bfloat16(v[j]);
        l[j] = __float2bfloat16(v[j] - __bfloat162float(h[j]));
    }
    *(uint4*)(hi + i) = *reinterpret_cast<uint4*>(h);
    *(uint4*)(lo + i) = *reinterpret_cast<uint4*>(l);
}

// ---------------------------------------------------------------------------
// Fused weight transpose + split: all 4 weights in one launch.
// ---------------------------------------------------------------------------
__global__ __launch_bounds__(256)
void transpose_split_all(const float* __restrict__ Wq, const float* __restrict__ Wk,
                         const float* __restrict__ Wv, const float* __restrict__ Wo,
                         bf16* __restrict__ Tqkv_hi, bf16* __restrict__ Tqkv_lo,
                         bf16* __restrict__ To_hi, bf16* __restrict__ To_lo) {
    __shared__ float s[32][33];
    const int z = blockIdx.z;
    const float* W = (z == 0) ? Wq : (z == 1) ? Wk : (z == 2) ? Wv : Wo;
    bf16* Thi = (z == 3) ? To_hi : Tqkv_hi;
    bf16* Tlo = (z == 3) ? To_lo : Tqkv_lo;
    const int rowoff = (z == 3) ? 0 : z * 1024;
    const float scale = (z == 0) ? 0.125f : 1.0f;

    int tx = threadIdx.x & 31, ty = threadIdx.x >> 5;
    int n0 = blockIdx.x * 32, k0 = blockIdx.y * 32;
#pragma unroll
    for (int i = 0; i < 4; i++)
        s[ty + i * 8][tx] = W[(size_t)(k0 + ty + i * 8) * 1024 + n0 + tx];
    __syncthreads();
#pragma unroll
    for (int i = 0; i < 4; i++) {
        float v = s[tx][ty + i * 8] * scale;
        bf16 h = __float2bfloat16(v);
        size_t o = (size_t)(rowoff + n0 + ty + i * 8) * 1024 + k0 + tx;
        Thi[o] = h;
        Tlo[o] = __float2bfloat16(v - __bfloat162float(h));
    }
}

// ---------------------------------------------------------------------------
// HMMA bf16x3 GEMM — R4 structure (2-stage, 80KB smem).
// MODE 0: out -> Q/K/V bf16 hi/lo [B,H,S,64]; MODE 1: fp32 [M,1024].
// ---------------------------------------------------------------------------
#define STGB 40960
#define SM_GEMM (2 * STGB)

template <int MODE>
__global__ __launch_bounds__(256)
void gemm_hmma(const bf16* __restrict__ Ahi, const bf16* __restrict__ Alo,
               const bf16* __restrict__ Bhi, const bf16* __restrict__ Blo,
               float* __restrict__ oF,
               bf16* __restrict__ qh, bf16* __restrict__ kh, bf16* __restrict__ vh,
               bf16* __restrict__ ql, bf16* __restrict__ kl, bf16* __restrict__ vl) {
    extern __shared__ char smc[];
    const uint32_t sb = smem_u32(smc);
    const int tid = threadIdx.x;
    const int wid = tid >> 5, lane = tid & 31;
    const int wm = wid >> 2, wn = wid & 3;
    const int m_base = wm * 64, n_base = wn * 32;
    const int bm = blockIdx.y * 128;
    const int bn = blockIdx.x * 128;

    float acc[4][4][4];
#pragma unroll
    for (int i = 0; i < 4; i++)
#pragma unroll
        for (int j = 0; j < 4; j++)
#pragma unroll
            for (int r = 0; r < 4; r++) acc[i][j][r] = 0.f;

    const uint32_t a_off = (uint32_t)(m_base + (lane & 15)) * 80 + (lane >> 4) * 16;
    const uint32_t b_off = (uint32_t)(n_base + ((lane >> 4) << 3) + (lane & 7)) * 80 +
                           ((lane >> 3) & 1) * 16;

    auto load_stage = [&](int s) {
        uint32_t ba = sb + (s & 1) * STGB;
        int k0 = s * 32;
#pragma unroll
        for (int it = 0; it < 2; it++) {
            int idx = tid + it * 256;
            int r = idx >> 2, c = idx & 3;
            uint32_t so = (uint32_t)r * 80 + c * 16;
            size_t goA = (size_t)(bm + r) * 1024 + k0 + c * 8;
            size_t goB = (size_t)(bn + r) * 1024 + k0 + c * 8;
            cpa16(ba + so, Ahi + goA);
            cpa16(ba + 10240 + so, Alo + goA);
            cpa16(ba + 20480 + so, Bhi + goB);
            cpa16(ba + 30720 + so, Blo + goB);
        }
        asm volatile("cp.async.commit_group;" ::: "memory");
    };

    load_stage(0);
    for (int s = 0; s < 32; s++) {
        if (s + 1 < 32) {
            load_stage(s + 1);
            asm volatile("cp.async.wait_group 1;" ::: "memory");
        } else {
            asm volatile("cp.async.wait_group 0;" ::: "memory");
        }
        __syncthreads();

        const uint32_t ba = sb + (s & 1) * STGB;
#pragma unroll
        for (int kk = 0; kk < 2; kk++) {
            const uint32_t kb = kk * 32;
            uint32_t ah[4][4], al[4][4], bh[4][2], bl[4][2];
#pragma unroll
            for (int mt = 0; mt < 4; mt++) {
                ldx4(ah[mt], ba + a_off + (uint32_t)mt * 16 * 80 + kb);
                ldx4(al[mt], ba + 10240 + a_off + (uint32_t)mt * 16 * 80 + kb);
            }
#pragma unroll
            for (int np = 0; np < 2; np++) {
                uint32_t t[4];
                ldx4(t, ba + 20480 + b_off + (uint32_t)np * 16 * 80 + kb);
                bh[np * 2][0] = t[0]; bh[np * 2][1] = t[1];
                bh[np * 2 + 1][0] = t[2]; bh[np * 2 + 1][1] = t[3];
                ldx4(t, ba + 30720 + b_off + (uint32_t)np * 16 * 80 + kb);
                bl[np * 2][0] = t[0]; bl[np * 2][1] = t[1];
                bl[np * 2 + 1][0] = t[2]; bl[np * 2 + 1][1] = t[3];
            }
#pragma unroll
            for (int mt = 0; mt < 4; mt++)
#pragma unroll
                for (int nt = 0; nt < 4; nt++) {
                    mma16816(acc[mt][nt], ah[mt], bh[nt]);
                    mma16816(acc[mt][nt], ah[mt], bl[nt]);
                    mma16816(acc[mt][nt], al[mt], bh[nt]);
                }
        }
        __syncthreads();
    }

#pragma unroll
    for (int mt = 0; mt < 4; mt++) {
#pragma unroll
        for (int half = 0; half < 2; half++) {
            int m = bm + m_base + mt * 16 + (lane >> 2) + half * 8;
#pragma unroll
            for (int nt = 0; nt < 4; nt++) {
                int c = n_base + nt * 8 + (lane & 3) * 2;
                float vx = acc[mt][nt][half * 2], vy = acc[mt][nt][half * 2 + 1];
                if (MODE == 0) {
                    int gcol = (bn & 1023) + c;
                    int matid = bn >> 10;
                    bf16* oh = (matid == 0) ? qh : (matid == 1) ? kh : vh;
                    bf16* ol = (matid == 0) ? ql : (matid == 1) ? kl : vl;
                    int h = gcol >> 6, d = gcol & 63;
                    int b = m >> 13, si = m & 8191;
                    size_t off = ((size_t)(b * HH + h) * SS + si) * 64 + d;
                    uint32_t ph, pl;
                    split2(vx, vy, ph, pl);
                    *(uint32_t*)&oh[off] = ph;
                    *(uint32_t*)&ol[off] = pl;
                } else {
                    *(float2*)&oF[(size_t)m * 1024 + bn + c] = make_float2(vx, vy);
                }
            }
        }
    }
}

// ---------------------------------------------------------------------------
// Banded attention on HMMA, bf16x3. 256 threads = 8 warps x 16 query rows.
// ---------------------------------------------------------------------------
#define AP 144
#define ATB 18432
#define SM_ATTN (4 * ATB)

__global__ __launch_bounds__(256)
void attn_tc(const bf16* __restrict__ Qhi, const bf16* __restrict__ Qlo,
             const bf16* __restrict__ Khi, const bf16* __restrict__ Klo,
             const bf16* __restrict__ Vhi, const bf16* __restrict__ Vlo,
             bf16* __restrict__ Ohi, bf16* __restrict__ Olo) {
    extern __shared__ char smc[];
    const uint32_t sb = smem_u32(smc);
    const int n = blockIdx.x, h = blockIdx.y, b = blockIdx.z;
    const int tid = threadIdx.x, w = tid >> 5, lane = tid & 31;
    const size_t head = (size_t)(b * HH + h) * SS * DK;
    const int qrow0 = n * 128;

    // Stage Q hi/lo (2 tiles x 1024 float4 / 256 threads = 4 chunks each)
#pragma unroll
    for (int it = 0; it < 4; it++) {
        int idx = tid + it * 256;
        int r = idx >> 3, c = idx & 7;
        uint32_t so = (uint32_t)r * AP + c * 16;
        size_t go = head + (size_t)(qrow0 + r) * 64 + c * 8;
        cpa16(sb + so, Qhi + go);
        cpa16(sb + ATB + so, Qlo + go);
    }
    asm volatile("cp.async.commit_group;\n\tcp.async.wait_group 0;" ::: "memory");
    __syncthreads();

    uint32_t qfh[4][4], qfl[4][4];
    const uint32_t a_off = (uint32_t)(w * 16 + (lane & 15)) * AP + (lane >> 4) * 16;
#pragma unroll
    for (int kt = 0; kt < 4; kt++) {
        ldx4(qfh[kt], sb + a_off + kt * 32);
        ldx4(qfl[kt], sb + ATB + a_off + kt * 32);
    }

    float o[8][4];
#pragma unroll
    for (int j = 0; j < 8; j++)
#pragma unroll
        for (int r = 0; r < 4; r++) o[j][r] = 0.f;
    float mrow[2] = {-1e30f, -1e30f};
    float lrow[2] = {0.f, 0.f};

    const uint32_t kb_off = (uint32_t)(((lane >> 4) << 3) + (lane & 7)) * AP +
                            ((lane >> 3) & 1) * 16;

    for (int kb = n - 1; kb <= n + 1; kb++) {
        if (kb < 0 || kb >= NB) continue;
        __syncthreads();
        const int j0k = kb * 128;
#pragma unroll
        for (int it = 0; it < 4; it++) {
            int idx = tid + it * 256;
            int r = idx >> 3, c = idx & 7;
            uint32_t so = (uint32_t)r * AP + c * 16;
            size_t go = head + (size_t)(j0k + r) * 64 + c * 8;
            cpa16(sb + so, Khi + go);
            cpa16(sb + ATB + so, Klo + go);
            cpa16(sb + 2 * ATB + so, Vhi + go);
            cpa16(sb + 3 * ATB + so, Vlo + go);
        }
        asm volatile("cp.async.commit_group;\n\tcp.async.wait_group 0;" ::: "memory");
        __syncthreads();

        for (int h2 = 0; h2 < 2; h2++) {
            // 16-row warps: prev-block first half valid only for rows 0-63;
            // next-block second half valid only for rows 64-127.
            if (kb == n - 1 && h2 == 0 && w >= 4) continue;
            if (kb == n + 1 && h2 == 1 && w < 4) continue;
            const int jbase = h2 * 64;

            // ---- scores S = Q K^T ----
            float sc[8][4];
#pragma unroll
            for (int j = 0; j < 8; j++)
#pragma unroll
                for (int r = 0; r < 4; r++) sc[j][r] = 0.f;

#pragma unroll
            for (int kt = 0; kt < 4; kt++) {
#pragma unroll
                for (int np = 0; np < 4; np++) {
                    uint32_t addr = kb_off + (uint32_t)(jbase + np * 16) * AP + kt * 32;
                    uint32_t th[4], tl[4];
                    ldx4(th, sb + addr);
                    ldx4(tl, sb + ATB + addr);
                    uint32_t bh0[2] = {th[0], th[1]}, bh1[2] = {th[2], th[3]};
                    uint32_t bl0[2] = {tl[0], tl[1]}, bl1[2] = {tl[2], tl[3]};
                    mma16816(sc[np * 2], qfh[kt], bh0);
                    mma16816(sc[np * 2], qfh[kt], bl0);
                    mma16816(sc[np * 2], qfl[kt], bh0);
                    mma16816(sc[np * 2 + 1], qfh[kt], bh1);
                    mma16816(sc[np * 2 + 1], qfh[kt], bl1);
                    mma16816(sc[np * 2 + 1], qfl[kt], bh1);
                }
            }

            // ---- mask + online softmax ----
            const int colbase = j0k + jbase + (lane & 3) * 2;
#pragma unroll
            for (int hf = 0; hf < 2; hf++) {
                const int i = qrow0 + w * 16 + (lane >> 2) + hf * 8;
                float mx = -1e30f;
#pragma unroll
                for (int nt = 0; nt < 8; nt++) {
#pragma unroll
                    for (int e = 0; e < 2; e++) {
                        int j = colbase + nt * 8 + e;
                        int d = j - i;
                        float s = sc[nt][hf * 2 + e];
                        s = (d >= -WW && d <= WW) ? s : -1e30f;
                        sc[nt][hf * 2 + e] = s;
                        mx = fmaxf(mx, s);
                    }
                }
                mx = fmaxf(mx, __shfl_xor_sync(0xffffffffu, mx, 1));
                mx = fmaxf(mx, __shfl_xor_sync(0xffffffffu, mx, 2));
                float mnew = fmaxf(mrow[hf], mx);
                float corr = __expf(mrow[hf] - mnew);
                mrow[hf] = mnew;
                float psum = 0.f;
#pragma unroll
                for (int nt = 0; nt < 8; nt++) {
#pragma unroll
                    for (int e = 0; e < 2; e++) {
                        float s = sc[nt][hf * 2 + e];
                        float p = (s < -1e29f) ? 0.f : __expf(s - mnew);
                        sc[nt][hf * 2 + e] = p;
                        psum += p;
                    }
                }
                psum += __shfl_xor_sync(0xffffffffu, psum, 1);
                psum += __shfl_xor_sync(0xffffffffu, psum, 2);
                lrow[hf] = lrow[hf] * corr + psum;
#pragma unroll
                for (int nt = 0; nt < 8; nt++) {
                    o[nt][hf * 2] *= corr;
                    o[nt][hf * 2 + 1] *= corr;
                }
            }

            // ---- P -> bf16 hi/lo A-frags ----
            uint32_t pfh[4][4], pfl[4][4];
#pragma unroll
            for (int kt = 0; kt < 4; kt++) {
                split2(sc[2 * kt][0], sc[2 * kt][1], pfh[kt][0], pfl[kt][0]);
                split2(sc[2 * kt][2], sc[2 * kt][3], pfh[kt][1], pfl[kt][1]);
                split2(sc[2 * kt + 1][0], sc[2 * kt + 1][1], pfh[kt][2], pfl[kt][2]);
                split2(sc[2 * kt + 1][2], sc[2 * kt + 1][3], pfh[kt][3], pfl[kt][3]);
            }

            // ---- O += P V ----
#pragma unroll
            for (int kt = 0; kt < 4; kt++) {
                const int k0 = jbase + kt * 16;
#pragma unroll
                for (int dp = 0; dp < 4; dp++) {
                    uint32_t vaddr =
                        (uint32_t)(k0 + (lane & 7) + ((lane >> 3) & 1) * 8) * AP +
                        (uint32_t)(dp * 16 + (lane >> 4) * 8) * 2;
                    uint32_t th[4], tl[4];
                    ldx4t(th, sb + 2 * ATB + vaddr);
                    ldx4t(tl, sb + 3 * ATB + vaddr);
                    uint32_t bh0[2] = {th[0], th[1]}, bh1[2] = {th[2], th[3]};
                    uint32_t bl0[2] = {tl[0], tl[1]}, bl1[2] = {tl[2], tl[3]};
                    mma16816(o[dp * 2], pfh[kt], bh0);
                    mma16816(o[dp * 2], pfl[kt], bh0);
                    mma16816(o[dp * 2], pfh[kt], bl0);
                    mma16816(o[dp * 2 + 1], pfh[kt], bh1);
                    mma16816(o[dp * 2 + 1], pfl[kt], bh1);
                    mma16816(o[dp * 2 + 1], pfh[kt], bl1);
                }
            }
        }
    }

    // ---- epilogue ----
#pragma unroll
    for (int hf = 0; hf < 2; hf++) {
        const float inv = 1.f / lrow[hf];
        const int i = qrow0 + w * 16 + (lane >> 2) + hf * 8;
        const size_t rowoff = ((size_t)b * SS + i) * 1024 + h * 64;
#pragma unroll
        for (int nt = 0; nt < 8; nt++) {
            int c = nt * 8 + (lane & 3) * 2;
            float vx = o[nt][hf * 2] * inv;
            float vy = o[nt][hf * 2 + 1] * inv;
            uint32_t ph, pl;
            split2(vx, vy, ph, pl);
            *(uint32_t*)&Ohi[rowoff + c] = ph;
            *(uint32_t*)&Olo[rowoff + c] = pl;
        }
    }
}

// ---------------------------------------------------------------------------
extern "C" void kernel_launch(void* const* d_in, const int* in_sizes, int n_in,
                              void* d_out, int out_size) {
    const float* x  = (const float*)d_in[0];
    const float* Wq = (const float*)d_in[1];
    const float* Wk = (const float*)d_in[2];
    const float* Wv = (const float*)d_in[3];
    const float* Wo = (const float*)d_in[4];
    float* out = (float*)d_out;

    bf16 *qh, *ql, *kh, *kl, *vh, *vl, *ahi, *alo, *wqh, *wql, *woh, *wol;
    cudaGetSymbolAddress((void**)&qh, g_qhi);
    cudaGetSymbolAddress((void**)&ql, g_qlo);
    cudaGetSymbolAddress((void**)&kh, g_khi);
    cudaGetSymbolAddress((void**)&kl, g_klo);
    cudaGetSymbolAddress((void**)&vh, g_vhi);
    cudaGetSymbolAddress((void**)&vl, g_vlo);
    cudaGetSymbolAddress((void**)&ahi, g_ahi);
    cudaGetSymbolAddress((void**)&alo, g_alo);
    cudaGetSymbolAddress((void**)&wqh, g_wqkv_hi);
    cudaGetSymbolAddress((void**)&wql, g_wqkv_lo);
    cudaGetSymbolAddress((void**)&woh, g_wo_hi);
    cudaGetSymbolAddress((void**)&wol, g_wo_lo);

    cudaFuncSetAttribute(gemm_hmma<0>, cudaFuncAttributeMaxDynamicSharedMemorySize, SM_GEMM);
    cudaFuncSetAttribute(gemm_hmma<1>, cudaFuncAttributeMaxDynamicSharedMemorySize, SM_GEMM);
    cudaFuncSetAttribute(attn_tc, cudaFuncAttributeMaxDynamicSharedMemorySize, SM_ATTN);

    convsplit<<<8192, 256>>>(x, ahi, alo);
    transpose_split_all<<<dim3(32, 32, 4), 256>>>(Wq, Wk, Wv, Wo, wqh, wql, woh, wol);

    gemm_hmma<0><<<dim3(24, 128), 256, SM_GEMM>>>(ahi, alo, wqh, wql, nullptr,
                                                  qh, kh, vh, ql, kl, vl);

    attn_tc<<<dim3(NB, HH, BB), 256, SM_ATTN>>>(qh, ql, kh, kl, vh, vl, ahi, alo);

    gemm_hmma<1><<<dim3(8, 128), 256, SM_GEMM>>>(ahi, alo, woh, wol, out,
                                                 nullptr, nullptr, nullptr,
                                                 nullptr, nullptr, nullptr);
}

// round 7
// speedup vs baseline: 1.5313x; 1.5313x over previous
#include <cuda_runtime.h>
#include <cuda_bf16.h>
#include <cstdint>

// Problem constants
#define BB 2
#define SS 8192
#define DD 1024
#define HH 16
#define DK 64
#define WW 128
#define NB (SS / 128)

typedef __nv_bfloat16 bf16;

// ---------------------------------------------------------------------------
// Scratch (device globals)
// ---------------------------------------------------------------------------
__device__ bf16 g_qhi[(size_t)BB * HH * SS * DK];
__device__ bf16 g_qlo[(size_t)BB * HH * SS * DK];
__device__ bf16 g_khi[(size_t)BB * HH * SS * DK];
__device__ bf16 g_klo[(size_t)BB * HH * SS * DK];
__device__ bf16 g_vhi[(size_t)BB * HH * SS * DK];
__device__ bf16 g_vlo[(size_t)BB * HH * SS * DK];
__device__ bf16 g_ahi[(size_t)16384 * 1024];
__device__ bf16 g_alo[(size_t)16384 * 1024];
__device__ bf16 g_wqkv_hi[(size_t)3072 * 1024];
__device__ bf16 g_wqkv_lo[(size_t)3072 * 1024];
__device__ bf16 g_wo_hi[(size_t)1024 * 1024];
__device__ bf16 g_wo_lo[(size_t)1024 * 1024];

// ---------------------------------------------------------------------------
// Helpers
// ---------------------------------------------------------------------------
__device__ __forceinline__ uint32_t smem_u32(const void* p) {
    uint32_t a;
    asm("{ .reg .u64 t; cvta.to.shared.u64 t, %1; cvt.u32.u64 %0, t; }"
        : "=r"(a) : "l"(p));
    return a;
}
__device__ __forceinline__ void cpa16(uint32_t s, const void* g) {
    asm volatile("cp.async.cg.shared.global [%0], [%1], 16;" :: "r"(s), "l"(g));
}
__device__ __forceinline__ void ldx4(uint32_t* r, uint32_t addr) {
    asm volatile("ldmatrix.sync.aligned.m8n8.x4.shared.b16 {%0,%1,%2,%3}, [%4];"
                 : "=r"(r[0]), "=r"(r[1]), "=r"(r[2]), "=r"(r[3]) : "r"(addr));
}
__device__ __forceinline__ void ldx4t(uint32_t* r, uint32_t addr) {
    asm volatile("ldmatrix.sync.aligned.m8n8.x4.trans.shared.b16 {%0,%1,%2,%3}, [%4];"
                 : "=r"(r[0]), "=r"(r[1]), "=r"(r[2]), "=r"(r[3]) : "r"(addr));
}
__device__ __forceinline__ void mma16816(float* c, const uint32_t* a,
                                         const uint32_t* b) {
    asm volatile(
        "mma.sync.aligned.m16n8k16.row.col.f32.bf16.bf16.f32 "
        "{%0,%1,%2,%3}, {%4,%5,%6,%7}, {%8,%9}, {%0,%1,%2,%3};"
        : "+f"(c[0]), "+f"(c[1]), "+f"(c[2]), "+f"(c[3])
        : "r"(a[0]), "r"(a[1]), "r"(a[2]), "r"(a[3]), "r"(b[0]), "r"(b[1]));
}
__device__ __forceinline__ uint32_t packbf2(bf16 a, bf16 b) {
    __nv_bfloat162 t;
    t.x = a; t.y = b;
    return *reinterpret_cast<uint32_t*>(&t);
}
__device__ __forceinline__ void split2(float a, float b, uint32_t& hi, uint32_t& lo) {
    bf16 ha = __float2bfloat16(a), hb = __float2bfloat16(b);
    bf16 la = __float2bfloat16(a - __bfloat162float(ha));
    bf16 lb = __float2bfloat16(b - __bfloat162float(hb));
    hi = packbf2(ha, hb);
    lo = packbf2(la, lb);
}

// ---------------------------------------------------------------------------
// Elementwise fp32 -> bf16 hi/lo split (for x)
// ---------------------------------------------------------------------------
__global__ __launch_bounds__(256)
void convsplit(const float* __restrict__ in, bf16* __restrict__ hi,
               bf16* __restrict__ lo) {
    size_t i = ((size_t)blockIdx.x * 256 + threadIdx.x) * 8;
    float4 a = *(const float4*)(in + i);
    float4 b = *(const float4*)(in + i + 4);
    float v[8] = {a.x, a.y, a.z, a.w, b.x, b.y, b.z, b.w};
    bf16 h[8], l[8];
#pragma unroll
    for (int j = 0; j < 8; j++) {
        h[j] = __float2bfloat16(v[j]);
        l[j] = __float2bfloat16(v[j] - __bfloat162float(h[j]));
    }
    *(uint4*)(hi + i) = *reinterpret_cast<uint4*>(h);
    *(uint4*)(lo + i) = *reinterpret_cast<uint4*>(l);
}

// ---------------------------------------------------------------------------
// Weight transpose + split (with scale): W[1024,N] -> T[N,1024] hi/lo bf16
// ---------------------------------------------------------------------------
__global__ __launch_bounds__(256)
void transpose_split(const float* __restrict__ W, bf16* __restrict__ Thi,
                     bf16* __restrict__ Tlo, int rowoff, float scale) {
    __shared__ float s[32][33];
    int tx = threadIdx.x & 31, ty = threadIdx.x >> 5;
    int n0 = blockIdx.x * 32, k0 = blockIdx.y * 32;
#pragma unroll
    for (int i = 0; i < 4; i++)
        s[ty + i * 8][tx] = W[(size_t)(k0 + ty + i * 8) * 1024 + n0 + tx];
    __syncthreads();
#pragma unroll
    for (int i = 0; i < 4; i++) {
        float v = s[tx][ty + i * 8] * scale;
        bf16 h = __float2bfloat16(v);
        size_t o = (size_t)(rowoff + n0 + ty + i * 8) * 1024 + k0 + tx;
        Thi[o] = h;
        Tlo[o] = __float2bfloat16(v - __bfloat162float(h));
    }
}

// ---------------------------------------------------------------------------
// HMMA bf16x3 GEMM — R4 structure (2-stage, 80KB smem).
// MODE 0: out -> Q/K/V bf16 hi/lo [B,H,S,64]; MODE 1: fp32 [M,1024].
// ---------------------------------------------------------------------------
#define STGB 40960
#define SM_GEMM (2 * STGB)

template <int MODE>
__global__ __launch_bounds__(256)
void gemm_hmma(const bf16* __restrict__ Ahi, const bf16* __restrict__ Alo,
               const bf16* __restrict__ Bhi, const bf16* __restrict__ Blo,
               float* __restrict__ oF,
               bf16* __restrict__ qh, bf16* __restrict__ kh, bf16* __restrict__ vh,
               bf16* __restrict__ ql, bf16* __restrict__ kl, bf16* __restrict__ vl) {
    extern __shared__ char smc[];
    const uint32_t sb = smem_u32(smc);
    const int tid = threadIdx.x;
    const int wid = tid >> 5, lane = tid & 31;
    const int wm = wid >> 2, wn = wid & 3;
    const int m_base = wm * 64, n_base = wn * 32;
    const int bm = blockIdx.y * 128;
    const int bn = blockIdx.x * 128;

    float acc[4][4][4];
#pragma unroll
    for (int i = 0; i < 4; i++)
#pragma unroll
        for (int j = 0; j < 4; j++)
#pragma unroll
            for (int r = 0; r < 4; r++) acc[i][j][r] = 0.f;

    const uint32_t a_off = (uint32_t)(m_base + (lane & 15)) * 80 + (lane >> 4) * 16;
    const uint32_t b_off = (uint32_t)(n_base + ((lane >> 4) << 3) + (lane & 7)) * 80 +
                           ((lane >> 3) & 1) * 16;

    auto load_stage = [&](int s) {
        uint32_t ba = sb + (s & 1) * STGB;
        int k0 = s * 32;
#pragma unroll
        for (int it = 0; it < 2; it++) {
            int idx = tid + it * 256;
            int r = idx >> 2, c = idx & 3;
            uint32_t so = (uint32_t)r * 80 + c * 16;
            size_t goA = (size_t)(bm + r) * 1024 + k0 + c * 8;
            size_t goB = (size_t)(bn + r) * 1024 + k0 + c * 8;
            cpa16(ba + so, Ahi + goA);
            cpa16(ba + 10240 + so, Alo + goA);
            cpa16(ba + 20480 + so, Bhi + goB);
            cpa16(ba + 30720 + so, Blo + goB);
        }
        asm volatile("cp.async.commit_group;" ::: "memory");
    };

    load_stage(0);
    for (int s = 0; s < 32; s++) {
        if (s + 1 < 32) {
            load_stage(s + 1);
            asm volatile("cp.async.wait_group 1;" ::: "memory");
        } else {
            asm volatile("cp.async.wait_group 0;" ::: "memory");
        }
        __syncthreads();

        const uint32_t ba = sb + (s & 1) * STGB;
#pragma unroll
        for (int kk = 0; kk < 2; kk++) {
            const uint32_t kb = kk * 32;
            uint32_t ah[4][4], al[4][4], bh[4][2], bl[4][2];
#pragma unroll
            for (int mt = 0; mt < 4; mt++) {
                ldx4(ah[mt], ba + a_off + (uint32_t)mt * 16 * 80 + kb);
                ldx4(al[mt], ba + 10240 + a_off + (uint32_t)mt * 16 * 80 + kb);
            }
#pragma unroll
            for (int np = 0; np < 2; np++) {
                uint32_t t[4];
                ldx4(t, ba + 20480 + b_off + (uint32_t)np * 16 * 80 + kb);
                bh[np * 2][0] = t[0]; bh[np * 2][1] = t[1];
                bh[np * 2 + 1][0] = t[2]; bh[np * 2 + 1][1] = t[3];
                ldx4(t, ba + 30720 + b_off + (uint32_t)np * 16 * 80 + kb);
                bl[np * 2][0] = t[0]; bl[np * 2][1] = t[1];
                bl[np * 2 + 1][0] = t[2]; bl[np * 2 + 1][1] = t[3];
            }
#pragma unroll
            for (int mt = 0; mt < 4; mt++)
#pragma unroll
                for (int nt = 0; nt < 4; nt++) {
                    mma16816(acc[mt][nt], ah[mt], bh[nt]);
                    mma16816(acc[mt][nt], ah[mt], bl[nt]);
                    mma16816(acc[mt][nt], al[mt], bh[nt]);
                }
        }
        __syncthreads();
    }

#pragma unroll
    for (int mt = 0; mt < 4; mt++) {
#pragma unroll
        for (int half = 0; half < 2; half++) {
            int m = bm + m_base + mt * 16 + (lane >> 2) + half * 8;
#pragma unroll
            for (int nt = 0; nt < 4; nt++) {
                int c = n_base + nt * 8 + (lane & 3) * 2;
                float vx = acc[mt][nt][half * 2], vy = acc[mt][nt][half * 2 + 1];
                if (MODE == 0) {
                    int gcol = (bn & 1023) + c;
                    int matid = bn >> 10;
                    bf16* oh = (matid == 0) ? qh : (matid == 1) ? kh : vh;
                    bf16* ol = (matid == 0) ? ql : (matid == 1) ? kl : vl;
                    int h = gcol >> 6, d = gcol & 63;
                    int b = m >> 13, si = m & 8191;
                    size_t off = ((size_t)(b * HH + h) * SS + si) * 64 + d;
                    uint32_t ph, pl;
                    split2(vx, vy, ph, pl);
                    *(uint32_t*)&oh[off] = ph;
                    *(uint32_t*)&ol[off] = pl;
                } else {
                    *(float2*)&oF[(size_t)m * 1024 + bn + c] = make_float2(vx, vy);
                }
            }
        }
    }
}

// ---------------------------------------------------------------------------
// Banded attention on HMMA (flash-attn-2 style), bf16x3 precision.
// 128 threads = 4 warps x 32 query rows (R4 configuration, 2 CTAs/SM).
// Scores are in base-2 domain (log2e folded into Wq) -> exp2f softmax.
// ---------------------------------------------------------------------------
#define AP 144
#define ATB 18432
#define SM_ATTN (4 * ATB)

__global__ __launch_bounds__(128)
void attn_tc(const bf16* __restrict__ Qhi, const bf16* __restrict__ Qlo,
             const bf16* __restrict__ Khi, const bf16* __restrict__ Klo,
             const bf16* __restrict__ Vhi, const bf16* __restrict__ Vlo,
             bf16* __restrict__ Ohi, bf16* __restrict__ Olo) {
    extern __shared__ char smc[];
    const uint32_t sb = smem_u32(smc);
    const int n = blockIdx.x, h = blockIdx.y, b = blockIdx.z;
    const int tid = threadIdx.x, w = tid >> 5, lane = tid & 31;
    const size_t head = (size_t)(b * HH + h) * SS * DK;
    const int qrow0 = n * 128;

#pragma unroll
    for (int it = 0; it < 8; it++) {
        int idx = tid + it * 128;
        int r = idx >> 3, c = idx & 7;
        uint32_t so = (uint32_t)r * AP + c * 16;
        size_t go = head + (size_t)(qrow0 + r) * 64 + c * 8;
        cpa16(sb + so, Qhi + go);
        cpa16(sb + ATB + so, Qlo + go);
    }
    asm volatile("cp.async.commit_group;\n\tcp.async.wait_group 0;" ::: "memory");
    __syncthreads();

    uint32_t qfh[2][4][4], qfl[2][4][4];
    const uint32_t a_off = (uint32_t)(w * 32 + (lane & 15)) * AP + (lane >> 4) * 16;
#pragma unroll
    for (int mt = 0; mt < 2; mt++)
#pragma unroll
        for (int kt = 0; kt < 4; kt++) {
            ldx4(qfh[mt][kt], sb + a_off + (uint32_t)mt * 16 * AP + kt * 32);
            ldx4(qfl[mt][kt], sb + ATB + a_off + (uint32_t)mt * 16 * AP + kt * 32);
        }

    float o[2][8][4];
#pragma unroll
    for (int i = 0; i < 2; i++)
#pragma unroll
        for (int j = 0; j < 8; j++)
#pragma unroll
            for (int r = 0; r < 4; r++) o[i][j][r] = 0.f;
    float mrow[4] = {-1e30f, -1e30f, -1e30f, -1e30f};
    float lrow[4] = {0.f, 0.f, 0.f, 0.f};

    const uint32_t kb_off = (uint32_t)(((lane >> 4) << 3) + (lane & 7)) * AP +
                            ((lane >> 3) & 1) * 16;

    for (int kb = n - 1; kb <= n + 1; kb++) {
        if (kb < 0 || kb >= NB) continue;
        __syncthreads();
        const int j0k = kb * 128;
#pragma unroll
        for (int it = 0; it < 8; it++) {
            int idx = tid + it * 128;
            int r = idx >> 3, c = idx & 7;
            uint32_t so = (uint32_t)r * AP + c * 16;
            size_t go = head + (size_t)(j0k + r) * 64 + c * 8;
            cpa16(sb + so, Khi + go);
            cpa16(sb + ATB + so, Klo + go);
            cpa16(sb + 2 * ATB + so, Vhi + go);
            cpa16(sb + 3 * ATB + so, Vlo + go);
        }
        asm volatile("cp.async.commit_group;\n\tcp.async.wait_group 0;" ::: "memory");
        __syncthreads();

        for (int h2 = 0; h2 < 2; h2++) {
            if (kb == n - 1 && h2 == 0 && w >= 2) continue;
            if (kb == n + 1 && h2 == 1 && w < 2) continue;
            const int jbase = h2 * 64;

            float sc[2][8][4];
#pragma unroll
            for (int i = 0; i < 2; i++)
#pragma unroll
                for (int j = 0; j < 8; j++)
#pragma unroll
                    for (int r = 0; r < 4; r++) sc[i][j][r] = 0.f;

#pragma unroll
            for (int kt = 0; kt < 4; kt++) {
#pragma unroll
                for (int np = 0; np < 4; np++) {
                    uint32_t addr = kb_off + (uint32_t)(jbase + np * 16) * AP + kt * 32;
                    uint32_t th[4], tl[4];
                    ldx4(th, sb + addr);
                    ldx4(tl, sb + ATB + addr);
                    uint32_t bh0[2] = {th[0], th[1]}, bh1[2] = {th[2], th[3]};
                    uint32_t bl0[2] = {tl[0], tl[1]}, bl1[2] = {tl[2], tl[3]};
#pragma unroll
                    for (int mt = 0; mt < 2; mt++) {
                        mma16816(sc[mt][np * 2], qfh[mt][kt], bh0);
                        mma16816(sc[mt][np * 2], qfh[mt][kt], bl0);
                        mma16816(sc[mt][np * 2], qfl[mt][kt], bh0);
                        mma16816(sc[mt][np * 2 + 1], qfh[mt][kt], bh1);
                        mma16816(sc[mt][np * 2 + 1], qfh[mt][kt], bl1);
                        mma16816(sc[mt][np * 2 + 1], qfl[mt][kt], bh1);
                    }
                }
            }

            const int colbase = j0k + jbase + (lane & 3) * 2;
#pragma unroll
            for (int mt = 0; mt < 2; mt++) {
#pragma unroll
                for (int hf = 0; hf < 2; hf++) {
                    const int i = qrow0 + w * 32 + mt * 16 + (lane >> 2) + hf * 8;
                    float mx = -1e30f;
#pragma unroll
                    for (int nt = 0; nt < 8; nt++) {
#pragma unroll
                        for (int e = 0; e < 2; e++) {
                            int j = colbase + nt * 8 + e;
                            int d = j - i;
                            float s = sc[mt][nt][hf * 2 + e];
                            s = (d >= -WW && d <= WW) ? s : -1e30f;
                            sc[mt][nt][hf * 2 + e] = s;
                            mx = fmaxf(mx, s);
                        }
                    }
                    mx = fmaxf(mx, __shfl_xor_sync(0xffffffffu, mx, 1));
                    mx = fmaxf(mx, __shfl_xor_sync(0xffffffffu, mx, 2));
                    const int slot = mt * 2 + hf;
                    float mnew = fmaxf(mrow[slot], mx);
                    float corr = exp2f(mrow[slot] - mnew);
                    mrow[slot] = mnew;
                    float psum = 0.f;
#pragma unroll
                    for (int nt = 0; nt < 8; nt++) {
#pragma unroll
                        for (int e = 0; e < 2; e++) {
                            float s = sc[mt][nt][hf * 2 + e];
                            float p = (s < -1e29f) ? 0.f : exp2f(s - mnew);
                            sc[mt][nt][hf * 2 + e] = p;
                            psum += p;
                        }
                    }
                    psum += __shfl_xor_sync(0xffffffffu, psum, 1);
                    psum += __shfl_xor_sync(0xffffffffu, psum, 2);
                    lrow[slot] = lrow[slot] * corr + psum;
#pragma unroll
                    for (int nt = 0; nt < 8; nt++) {
                        o[mt][nt][hf * 2] *= corr;
                        o[mt][nt][hf * 2 + 1] *= corr;
                    }
                }
            }

            uint32_t pfh[2][4][4], pfl[2][4][4];
#pragma unroll
            for (int mt = 0; mt < 2; mt++)
#pragma unroll
                for (int kt = 0; kt < 4; kt++) {
                    split2(sc[mt][2 * kt][0], sc[mt][2 * kt][1],
                           pfh[mt][kt][0], pfl[mt][kt][0]);
                    split2(sc[mt][2 * kt][2], sc[mt][2 * kt][3],
                           pfh[mt][kt][1], pfl[mt][kt][1]);
                    split2(sc[mt][2 * kt + 1][0], sc[mt][2 * kt + 1][1],
                           pfh[mt][kt][2], pfl[mt][kt][2]);
                    split2(sc[mt][2 * kt + 1][2], sc[mt][2 * kt + 1][3],
                           pfh[mt][kt][3], pfl[mt][kt][3]);
                }

#pragma unroll
            for (int kt = 0; kt < 4; kt++) {
                const int k0 = jbase + kt * 16;
#pragma unroll
                for (int dp = 0; dp < 4; dp++) {
                    uint32_t vaddr =
                        (uint32_t)(k0 + (lane & 7) + ((lane >> 3) & 1) * 8) * AP +
                        (uint32_t)(dp * 16 + (lane >> 4) * 8) * 2;
                    uint32_t th[4], tl[4];
                    ldx4t(th, sb + 2 * ATB + vaddr);
                    ldx4t(tl, sb + 3 * ATB + vaddr);
                    uint32_t bh0[2] = {th[0], th[1]}, bh1[2] = {th[2], th[3]};
                    uint32_t bl0[2] = {tl[0], tl[1]}, bl1[2] = {tl[2], tl[3]};
#pragma unroll
                    for (int mt = 0; mt < 2; mt++) {
                        mma16816(o[mt][dp * 2], pfh[mt][kt], bh0);
                        mma16816(o[mt][dp * 2], pfl[mt][kt], bh0);
                        mma16816(o[mt][dp * 2], pfh[mt][kt], bl0);
                        mma16816(o[mt][dp * 2 + 1], pfh[mt][kt], bh1);
                        mma16816(o[mt][dp * 2 + 1], pfl[mt][kt], bh1);
                        mma16816(o[mt][dp * 2 + 1], pfh[mt][kt], bl1);
                    }
                }
            }
        }
    }

#pragma unroll
    for (int mt = 0; mt < 2; mt++) {
#pragma unroll
        for (int hf = 0; hf < 2; hf++) {
            const int slot = mt * 2 + hf;
            const float inv = 1.f / lrow[slot];
            const int i = qrow0 + w * 32 + mt * 16 + (lane >> 2) + hf * 8;
            const size_t rowoff = ((size_t)b * SS + i) * 1024 + h * 64;
#pragma unroll
            for (int nt = 0; nt < 8; nt++) {
                int c = nt * 8 + (lane & 3) * 2;
                float vx = o[mt][nt][hf * 2] * inv;
                float vy = o[mt][nt][hf * 2 + 1] * inv;
                uint32_t ph, pl;
                split2(vx, vy, ph, pl);
                *(uint32_t*)&Ohi[rowoff + c] = ph;
                *(uint32_t*)&Olo[rowoff + c] = pl;
            }
        }
    }
}

// ---------------------------------------------------------------------------
extern "C" void kernel_launch(void* const* d_in, const int* in_sizes, int n_in,
                              void* d_out, int out_size) {
    const float* x  = (const float*)d_in[0];
    const float* Wq = (const float*)d_in[1];
    const float* Wk = (const float*)d_in[2];
    const float* Wv = (const float*)d_in[3];
    const float* Wo = (const float*)d_in[4];
    float* out = (float*)d_out;

    bf16 *qh, *ql, *kh, *kl, *vh, *vl, *ahi, *alo, *wqh, *wql, *woh, *wol;
    cudaGetSymbolAddress((void**)&qh, g_qhi);
    cudaGetSymbolAddress((void**)&ql, g_qlo);
    cudaGetSymbolAddress((void**)&kh, g_khi);
    cudaGetSymbolAddress((void**)&kl, g_klo);
    cudaGetSymbolAddress((void**)&vh, g_vhi);
    cudaGetSymbolAddress((void**)&vl, g_vlo);
    cudaGetSymbolAddress((void**)&ahi, g_ahi);
    cudaGetSymbolAddress((void**)&alo, g_alo);
    cudaGetSymbolAddress((void**)&wqh, g_wqkv_hi);
    cudaGetSymbolAddress((void**)&wql, g_wqkv_lo);
    cudaGetSymbolAddress((void**)&woh, g_wo_hi);
    cudaGetSymbolAddress((void**)&wol, g_wo_lo);

    cudaFuncSetAttribute(gemm_hmma<0>, cudaFuncAttributeMaxDynamicSharedMemorySize, SM_GEMM);
    cudaFuncSetAttribute(gemm_hmma<1>, cudaFuncAttributeMaxDynamicSharedMemorySize, SM_GEMM);
    cudaFuncSetAttribute(attn_tc, cudaFuncAttributeMaxDynamicSharedMemorySize, SM_ATTN);

    convsplit<<<8192, 256>>>(x, ahi, alo);
    // 0.125 * log2(e): scores land in base-2 domain for exp2f softmax
    transpose_split<<<dim3(32, 32), 256>>>(Wq, wqh, wql, 0, 0.18033688f);
    transpose_split<<<dim3(32, 32), 256>>>(Wk, wqh, wql, 1024, 1.0f);
    transpose_split<<<dim3(32, 32), 256>>>(Wv, wqh, wql, 2048, 1.0f);
    transpose_split<<<dim3(32, 32), 256>>>(Wo, woh, wol, 0, 1.0f);

    gemm_hmma<0><<<dim3(24, 128), 256, SM_GEMM>>>(ahi, alo, wqh, wql, nullptr,
                                                  qh, kh, vh, ql, kl, vl);

    attn_tc<<<dim3(NB, HH, BB), 128, SM_ATTN>>>(qh, ql, kh, kl, vh, vl, ahi, alo);

    gemm_hmma<1><<<dim3(8, 128), 256, SM_GEMM>>>(ahi, alo, woh, wol, out,
                                                 nullptr, nullptr, nullptr,
                                                 nullptr, nullptr, nullptr);
}

// round 14
// speedup vs baseline: 1.5460x; 1.0096x over previous
#include <cuda_runtime.h>
#include <cuda_bf16.h>
#include <cstdint>

// Problem constants
#define BB 2
#define SS 8192
#define DD 1024
#define HH 16
#define DK 64
#define WW 128
#define NB (SS / 128)

typedef __nv_bfloat16 bf16;

// ---------------------------------------------------------------------------
// Scratch (device globals)
// ---------------------------------------------------------------------------
__device__ bf16 g_qhi[(size_t)BB * HH * SS * DK];
__device__ bf16 g_qlo[(size_t)BB * HH * SS * DK];
__device__ bf16 g_khi[(size_t)BB * HH * SS * DK];
__device__ bf16 g_klo[(size_t)BB * HH * SS * DK];
__device__ bf16 g_vhi[(size_t)BB * HH * SS * DK];
__device__ bf16 g_vlo[(size_t)BB * HH * SS * DK];
__device__ bf16 g_ahi[(size_t)16384 * 1024];
__device__ bf16 g_alo[(size_t)16384 * 1024];
__device__ bf16 g_wqkv_hi[(size_t)3072 * 1024];
__device__ bf16 g_wqkv_lo[(size_t)3072 * 1024];
__device__ bf16 g_wo_hi[(size_t)1024 * 1024];
__device__ bf16 g_wo_lo[(size_t)1024 * 1024];

// ---------------------------------------------------------------------------
// Helpers
// ---------------------------------------------------------------------------
__device__ __forceinline__ uint32_t smem_u32(const void* p) {
    uint32_t a;
    asm("{ .reg .u64 t; cvta.to.shared.u64 t, %1; cvt.u32.u64 %0, t; }"
        : "=r"(a) : "l"(p));
    return a;
}
__device__ __forceinline__ void cpa16(uint32_t s, const void* g) {
    asm volatile("cp.async.cg.shared.global [%0], [%1], 16;" :: "r"(s), "l"(g));
}
__device__ __forceinline__ void ldx4(uint32_t* r, uint32_t addr) {
    asm volatile("ldmatrix.sync.aligned.m8n8.x4.shared.b16 {%0,%1,%2,%3}, [%4];"
                 : "=r"(r[0]), "=r"(r[1]), "=r"(r[2]), "=r"(r[3]) : "r"(addr));
}
__device__ __forceinline__ void ldx4t(uint32_t* r, uint32_t addr) {
    asm volatile("ldmatrix.sync.aligned.m8n8.x4.trans.shared.b16 {%0,%1,%2,%3}, [%4];"
                 : "=r"(r[0]), "=r"(r[1]), "=r"(r[2]), "=r"(r[3]) : "r"(addr));
}
__device__ __forceinline__ void mma16816(float* c, const uint32_t* a,
                                         const uint32_t* b) {
    asm volatile(
        "mma.sync.aligned.m16n8k16.row.col.f32.bf16.bf16.f32 "
        "{%0,%1,%2,%3}, {%4,%5,%6,%7}, {%8,%9}, {%0,%1,%2,%3};"
        : "+f"(c[0]), "+f"(c[1]), "+f"(c[2]), "+f"(c[3])
        : "r"(a[0]), "r"(a[1]), "r"(a[2]), "r"(a[3]), "r"(b[0]), "r"(b[1]));
}
__device__ __forceinline__ uint32_t packbf2(bf16 a, bf16 b) {
    __nv_bfloat162 t;
    t.x = a; t.y = b;
    return *reinterpret_cast<uint32_t*>(&t);
}
__device__ __forceinline__ void split2(float a, float b, uint32_t& hi, uint32_t& lo) {
    bf16 ha = __float2bfloat16(a), hb = __float2bfloat16(b);
    bf16 la = __float2bfloat16(a - __bfloat162float(ha));
    bf16 lb = __float2bfloat16(b - __bfloat162float(hb));
    hi = packbf2(ha, hb);
    lo = packbf2(la, lb);
}

// ---------------------------------------------------------------------------
// Elementwise fp32 -> bf16 hi/lo split (for x)
// ---------------------------------------------------------------------------
__global__ __launch_bounds__(256)
void convsplit(const float* __restrict__ in, bf16* __restrict__ hi,
               bf16* __restrict__ lo) {
    size_t i = ((size_t)blockIdx.x * 256 + threadIdx.x) * 8;
    float4 a = *(const float4*)(in + i);
    float4 b = *(const float4*)(in + i + 4);
    float v[8] = {a.x, a.y, a.z, a.w, b.x, b.y, b.z, b.w};
    bf16 h[8], l[8];
#pragma unroll
    for (int j = 0; j < 8; j++) {
        h[j] = __float2bfloat16(v[j]);
        l[j] = __float2bfloat16(v[j] - __bfloat162float(h[j]));
    }
    *(uint4*)(hi + i) = *reinterpret_cast<uint4*>(h);
    *(uint4*)(lo + i) = *reinterpret_cast<uint4*>(l);
}

// ---------------------------------------------------------------------------
// Weight transpose + split (with scale): W[1024,N] -> T[N,1024] hi/lo bf16
// ---------------------------------------------------------------------------
__global__ __launch_bounds__(256)
void transpose_split(const float* __restrict__ W, bf16* __restrict__ Thi,
                     bf16* __restrict__ Tlo, int rowoff, float scale) {
    __shared__ float s[32][33];
    int tx = threadIdx.x & 31, ty = threadIdx.x >> 5;
    int n0 = blockIdx.x * 32, k0 = blockIdx.y * 32;
#pragma unroll
    for (int i = 0; i < 4; i++)
        s[ty + i * 8][tx] = W[(size_t)(k0 + ty + i * 8) * 1024 + n0 + tx];
    __syncthreads();
#pragma unroll
    for (int i = 0; i < 4; i++) {
        float v = s[tx][ty + i * 8] * scale;
        bf16 h = __float2bfloat16(v);
        size_t o = (size_t)(rowoff + n0 + ty + i * 8) * 1024 + k0 + tx;
        Thi[o] = h;
        Tlo[o] = __float2bfloat16(v - __bfloat162float(h));
    }
}

// ---------------------------------------------------------------------------
// HMMA bf16x3 GEMM — frozen R4 structure (2-stage, 80KB smem).
// MODE 0: out -> Q/K/V bf16 hi/lo [B,H,S,64]; MODE 1: fp32 [M,1024].
// ---------------------------------------------------------------------------
#define STGB 40960
#define SM_GEMM (2 * STGB)

template <int MODE>
__global__ __launch_bounds__(256)
void gemm_hmma(const bf16* __restrict__ Ahi, const bf16* __restrict__ Alo,
               const bf16* __restrict__ Bhi, const bf16* __restrict__ Blo,
               float* __restrict__ oF,
               bf16* __restrict__ qh, bf16* __restrict__ kh, bf16* __restrict__ vh,
               bf16* __restrict__ ql, bf16* __restrict__ kl, bf16* __restrict__ vl) {
    extern __shared__ char smc[];
    const uint32_t sb = smem_u32(smc);
    const int tid = threadIdx.x;
    const int wid = tid >> 5, lane = tid & 31;
    const int wm = wid >> 2, wn = wid & 3;
    const int m_base = wm * 64, n_base = wn * 32;
    const int bm = blockIdx.y * 128;
    const int bn = blockIdx.x * 128;

    float acc[4][4][4];
#pragma unroll
    for (int i = 0; i < 4; i++)
#pragma unroll
        for (int j = 0; j < 4; j++)
#pragma unroll
            for (int r = 0; r < 4; r++) acc[i][j][r] = 0.f;

    const uint32_t a_off = (uint32_t)(m_base + (lane & 15)) * 80 + (lane >> 4) * 16;
    const uint32_t b_off = (uint32_t)(n_base + ((lane >> 4) << 3) + (lane & 7)) * 80 +
                           ((lane >> 3) & 1) * 16;

    auto load_stage = [&](int s) {
        uint32_t ba = sb + (s & 1) * STGB;
        int k0 = s * 32;
#pragma unroll
        for (int it = 0; it < 2; it++) {
            int idx = tid + it * 256;
            int r = idx >> 2, c = idx & 3;
            uint32_t so = (uint32_t)r * 80 + c * 16;
            size_t goA = (size_t)(bm + r) * 1024 + k0 + c * 8;
            size_t goB = (size_t)(bn + r) * 1024 + k0 + c * 8;
            cpa16(ba + so, Ahi + goA);
            cpa16(ba + 10240 + so, Alo + goA);
            cpa16(ba + 20480 + so, Bhi + goB);
            cpa16(ba + 30720 + so, Blo + goB);
        }
        asm volatile("cp.async.commit_group;" ::: "memory");
    };

    load_stage(0);
    for (int s = 0; s < 32; s++) {
        if (s + 1 < 32) {
            load_stage(s + 1);
            asm volatile("cp.async.wait_group 1;" ::: "memory");
        } else {
            asm volatile("cp.async.wait_group 0;" ::: "memory");
        }
        __syncthreads();

        const uint32_t ba = sb + (s & 1) * STGB;
#pragma unroll
        for (int kk = 0; kk < 2; kk++) {
            const uint32_t kb = kk * 32;
            uint32_t ah[4][4], al[4][4], bh[4][2], bl[4][2];
#pragma unroll
            for (int mt = 0; mt < 4; mt++) {
                ldx4(ah[mt], ba + a_off + (uint32_t)mt * 16 * 80 + kb);
                ldx4(al[mt], ba + 10240 + a_off + (uint32_t)mt * 16 * 80 + kb);
            }
#pragma unroll
            for (int np = 0; np < 2; np++) {
                uint32_t t[4];
                ldx4(t, ba + 20480 + b_off + (uint32_t)np * 16 * 80 + kb);
                bh[np * 2][0] = t[0]; bh[np * 2][1] = t[1];
                bh[np * 2 + 1][0] = t[2]; bh[np * 2 + 1][1] = t[3];
                ldx4(t, ba + 30720 + b_off + (uint32_t)np * 16 * 80 + kb);
                bl[np * 2][0] = t[0]; bl[np * 2][1] = t[1];
                bl[np * 2 + 1][0] = t[2]; bl[np * 2 + 1][1] = t[3];
            }
#pragma unroll
            for (int mt = 0; mt < 4; mt++)
#pragma unroll
                for (int nt = 0; nt < 4; nt++) {
                    mma16816(acc[mt][nt], ah[mt], bh[nt]);
                    mma16816(acc[mt][nt], ah[mt], bl[nt]);
                    mma16816(acc[mt][nt], al[mt], bh[nt]);
                }
        }
        __syncthreads();
    }

#pragma unroll
    for (int mt = 0; mt < 4; mt++) {
#pragma unroll
        for (int half = 0; half < 2; half++) {
            int m = bm + m_base + mt * 16 + (lane >> 2) + half * 8;
#pragma unroll
            for (int nt = 0; nt < 4; nt++) {
                int c = n_base + nt * 8 + (lane & 3) * 2;
                float vx = acc[mt][nt][half * 2], vy = acc[mt][nt][half * 2 + 1];
                if (MODE == 0) {
                    int gcol = (bn & 1023) + c;
                    int matid = bn >> 10;
                    bf16* oh = (matid == 0) ? qh : (matid == 1) ? kh : vh;
                    bf16* ol = (matid == 0) ? ql : (matid == 1) ? kl : vl;
                    int h = gcol >> 6, d = gcol & 63;
                    int b = m >> 13, si = m & 8191;
                    size_t off = ((size_t)(b * HH + h) * SS + si) * 64 + d;
                    uint32_t ph, pl;
                    split2(vx, vy, ph, pl);
                    *(uint32_t*)&oh[off] = ph;
                    *(uint32_t*)&ol[off] = pl;
                } else {
                    *(float2*)&oF[(size_t)m * 1024 + bn + c] = make_float2(vx, vy);
                }
            }
        }
    }
}

// ---------------------------------------------------------------------------
// Banded attention on HMMA, bf16x3. 128 threads = 4 warps x 32 query rows.
// K double-buffered (cross-block prefetch); V load overlaps h2=0 QK+softmax.
// Correct online-softmax order: per half, QK -> softmax -> P·V immediately.
// Smem: K0 hi|lo, K1 hi|lo, V hi|lo (Q stages through the V buffers).
// ---------------------------------------------------------------------------
#define AP 144
#define ATB 18432
#define SM_ATTN (6 * ATB)

__global__ __launch_bounds__(128)
void attn_tc(const bf16* __restrict__ Qhi, const bf16* __restrict__ Qlo,
             const bf16* __restrict__ Khi, const bf16* __restrict__ Klo,
             const bf16* __restrict__ Vhi, const bf16* __restrict__ Vlo,
             bf16* __restrict__ Ohi, bf16* __restrict__ Olo) {
    extern __shared__ char smc[];
    const uint32_t sb = smem_u32(smc);
    const int n = blockIdx.x, h = blockIdx.y, b = blockIdx.z;
    const int tid = threadIdx.x, w = tid >> 5, lane = tid & 31;
    const size_t head = (size_t)(b * HH + h) * SS * DK;
    const int qrow0 = n * 128;

    const uint32_t VB = sb + 4 * ATB;

    // ---- Stage Q through the V buffers, consume into registers ----
#pragma unroll
    for (int it = 0; it < 8; it++) {
        int idx = tid + it * 128;
        int r = idx >> 3, c = idx & 7;
        uint32_t so = (uint32_t)r * AP + c * 16;
        size_t go = head + (size_t)(qrow0 + r) * 64 + c * 8;
        cpa16(VB + so, Qhi + go);
        cpa16(VB + ATB + so, Qlo + go);
    }
    asm volatile("cp.async.commit_group;\n\tcp.async.wait_group 0;" ::: "memory");
    __syncthreads();

    uint32_t qfh[2][4][4], qfl[2][4][4];
    const uint32_t a_off = (uint32_t)(w * 32 + (lane & 15)) * AP + (lane >> 4) * 16;
#pragma unroll
    for (int mt = 0; mt < 2; mt++)
#pragma unroll
        for (int kt = 0; kt < 4; kt++) {
            ldx4(qfh[mt][kt], VB + a_off + (uint32_t)mt * 16 * AP + kt * 32);
            ldx4(qfl[mt][kt], VB + ATB + a_off + (uint32_t)mt * 16 * AP + kt * 32);
        }
    __syncthreads();   // Q consumed; V buffer free for overwrite

    auto load_K = [&](int kb, int buf) {
        const uint32_t KB = sb + buf * 2 * ATB;
        const int j0k = kb * 128;
#pragma unroll
        for (int it = 0; it < 8; it++) {
            int idx = tid + it * 128;
            int r = idx >> 3, c = idx & 7;
            uint32_t so = (uint32_t)r * AP + c * 16;
            size_t go = head + (size_t)(j0k + r) * 64 + c * 8;
            cpa16(KB + so, Khi + go);
            cpa16(KB + ATB + so, Klo + go);
        }
        asm volatile("cp.async.commit_group;" ::: "memory");
    };
    auto load_V = [&](int kb) {
        const int j0k = kb * 128;
#pragma unroll
        for (int it = 0; it < 8; it++) {
            int idx = tid + it * 128;
            int r = idx >> 3, c = idx & 7;
            uint32_t so = (uint32_t)r * AP + c * 16;
            size_t go = head + (size_t)(j0k + r) * 64 + c * 8;
            cpa16(VB + so, Vhi + go);
            cpa16(VB + ATB + so, Vlo + go);
        }
        asm volatile("cp.async.commit_group;" ::: "memory");
    };

    float o[2][8][4];
#pragma unroll
    for (int i = 0; i < 2; i++)
#pragma unroll
        for (int j = 0; j < 8; j++)
#pragma unroll
            for (int r = 0; r < 4; r++) o[i][j][r] = 0.f;
    float mrow[4] = {-1e30f, -1e30f, -1e30f, -1e30f};
    float lrow[4] = {0.f, 0.f, 0.f, 0.f};

    const uint32_t kb_off = (uint32_t)(((lane >> 4) << 3) + (lane & 7)) * AP +
                            ((lane >> 3) & 1) * 16;

    const int kb_first = (n == 0) ? 0 : n - 1;
    const int kb_last = (n == NB - 1) ? n : n + 1;

    load_K(kb_first, 0);   // prologue prefetch

    int kcur = 0;
    for (int kb = kb_first; kb <= kb_last; kb++, kcur ^= 1) {
        load_V(kb);
        load_K((kb < kb_last) ? kb + 1 : kb_last, kcur ^ 1);
        asm volatile("cp.async.wait_group 2;" ::: "memory");   // K(kb) ready
        __syncthreads();

        const int j0k = kb * 128;
        const uint32_t KB = sb + kcur * 2 * ATB;

        for (int h2 = 0; h2 < 2; h2++) {
            const bool act = !((kb == n - 1 && h2 == 0 && w >= 2) ||
                               (kb == n + 1 && h2 == 1 && w < 2));
            const int jbase = h2 * 64;
            uint32_t pfh[2][4][4], pfl[2][4][4];

            if (act) {
                // ---- scores S = Q K^T ----
                float sc[2][8][4];
#pragma unroll
                for (int i = 0; i < 2; i++)
#pragma unroll
                    for (int j = 0; j < 8; j++)
#pragma unroll
                        for (int r = 0; r < 4; r++) sc[i][j][r] = 0.f;

#pragma unroll
                for (int kt = 0; kt < 4; kt++) {
#pragma unroll
                    for (int np = 0; np < 4; np++) {
                        uint32_t addr = kb_off + (uint32_t)(jbase + np * 16) * AP + kt * 32;
                        uint32_t th[4], tl[4];
                        ldx4(th, KB + addr);
                        ldx4(tl, KB + ATB + addr);
                        uint32_t bh0[2] = {th[0], th[1]}, bh1[2] = {th[2], th[3]};
                        uint32_t bl0[2] = {tl[0], tl[1]}, bl1[2] = {tl[2], tl[3]};
#pragma unroll
                        for (int mt = 0; mt < 2; mt++) {
                            mma16816(sc[mt][np * 2], qfh[mt][kt], bh0);
                            mma16816(sc[mt][np * 2], qfh[mt][kt], bl0);
                            mma16816(sc[mt][np * 2], qfl[mt][kt], bh0);
                            mma16816(sc[mt][np * 2 + 1], qfh[mt][kt], bh1);
                            mma16816(sc[mt][np * 2 + 1], qfh[mt][kt], bl1);
                            mma16816(sc[mt][np * 2 + 1], qfl[mt][kt], bh1);
                        }
                    }
                }

                // ---- mask + online softmax ----
                const int colbase = j0k + jbase + (lane & 3) * 2;
#pragma unroll
                for (int mt = 0; mt < 2; mt++) {
#pragma unroll
                    for (int hf = 0; hf < 2; hf++) {
                        const int i = qrow0 + w * 32 + mt * 16 + (lane >> 2) + hf * 8;
                        float mx = -1e30f;
#pragma unroll
                        for (int nt = 0; nt < 8; nt++) {
#pragma unroll
                            for (int e = 0; e < 2; e++) {
                                int j = colbase + nt * 8 + e;
                                int d = j - i;
                                float s = sc[mt][nt][hf * 2 + e];
                                s = (d >= -WW && d <= WW) ? s : -1e30f;
                                sc[mt][nt][hf * 2 + e] = s;
                                mx = fmaxf(mx, s);
                            }
                        }
                        mx = fmaxf(mx, __shfl_xor_sync(0xffffffffu, mx, 1));
                        mx = fmaxf(mx, __shfl_xor_sync(0xffffffffu, mx, 2));
                        const int slot = mt * 2 + hf;
                        float mnew = fmaxf(mrow[slot], mx);
                        float corr = exp2f(mrow[slot] - mnew);
                        mrow[slot] = mnew;
                        float psum = 0.f;
#pragma unroll
                        for (int nt = 0; nt < 8; nt++) {
#pragma unroll
                            for (int e = 0; e < 2; e++) {
                                float s = sc[mt][nt][hf * 2 + e];
                                float p = (s < -1e29f) ? 0.f : exp2f(s - mnew);
                                sc[mt][nt][hf * 2 + e] = p;
                                psum += p;
                            }
                        }
                        psum += __shfl_xor_sync(0xffffffffu, psum, 1);
                        psum += __shfl_xor_sync(0xffffffffu, psum, 2);
                        lrow[slot] = lrow[slot] * corr + psum;
#pragma unroll
                        for (int nt = 0; nt < 8; nt++) {
                            o[mt][nt][hf * 2] *= corr;
                            o[mt][nt][hf * 2 + 1] *= corr;
                        }
                    }
                }

                // ---- P -> bf16 hi/lo A-frags ----
#pragma unroll
                for (int mt = 0; mt < 2; mt++)
#pragma unroll
                    for (int kt = 0; kt < 4; kt++) {
                        split2(sc[mt][2 * kt][0], sc[mt][2 * kt][1],
                               pfh[mt][kt][0], pfl[mt][kt][0]);
                        split2(sc[mt][2 * kt][2], sc[mt][2 * kt][3],
                               pfh[mt][kt][1], pfl[mt][kt][1]);
                        split2(sc[mt][2 * kt + 1][0], sc[mt][2 * kt + 1][1],
                               pfh[mt][kt][2], pfl[mt][kt][2]);
                        split2(sc[mt][2 * kt + 1][2], sc[mt][2 * kt + 1][3],
                               pfh[mt][kt][3], pfl[mt][kt][3]);
                    }
            }

            if (h2 == 0) {
                // V load was overlapped with QK(h2=0) + softmax; now required.
                asm volatile("cp.async.wait_group 1;" ::: "memory");
                __syncthreads();
            }

            if (act) {
                // ---- O += P V ----
#pragma unroll
                for (int kt = 0; kt < 4; kt++) {
                    const int k0 = jbase + kt * 16;
#pragma unroll
                    for (int dp = 0; dp < 4; dp++) {
                        uint32_t vaddr =
                            (uint32_t)(k0 + (lane & 7) + ((lane >> 3) & 1) * 8) * AP +
                            (uint32_t)(dp * 16 + (lane >> 4) * 8) * 2;
                        uint32_t th[4], tl[4];
                        ldx4t(th, VB + vaddr);
                        ldx4t(tl, VB + ATB + vaddr);
                        uint32_t bh0[2] = {th[0], th[1]}, bh1[2] = {th[2], th[3]};
                        uint32_t bl0[2] = {tl[0], tl[1]}, bl1[2] = {tl[2], tl[3]};
#pragma unroll
                        for (int mt = 0; mt < 2; mt++) {
                            mma16816(o[mt][dp * 2], pfh[mt][kt], bh0);
                            mma16816(o[mt][dp * 2], pfl[mt][kt], bh0);
                            mma16816(o[mt][dp * 2], pfh[mt][kt], bl0);
                            mma16816(o[mt][dp * 2 + 1], pfh[mt][kt], bh1);
                            mma16816(o[mt][dp * 2 + 1], pfl[mt][kt], bh1);
                            mma16816(o[mt][dp * 2 + 1], pfh[mt][kt], bl1);
                        }
                    }
                }
            }
        }
        __syncthreads();   // V/K consumed before next iteration overwrites
    }

#pragma unroll
    for (int mt = 0; mt < 2; mt++) {
#pragma unroll
        for (int hf = 0; hf < 2; hf++) {
            const int slot = mt * 2 + hf;
            const float inv = 1.f / lrow[slot];
            const int i = qrow0 + w * 32 + mt * 16 + (lane >> 2) + hf * 8;
            const size_t rowoff = ((size_t)b * SS + i) * 1024 + h * 64;
#pragma unroll
            for (int nt = 0; nt < 8; nt++) {
                int c = nt * 8 + (lane & 3) * 2;
                float vx = o[mt][nt][hf * 2] * inv;
                float vy = o[mt][nt][hf * 2 + 1] * inv;
                uint32_t ph, pl;
                split2(vx, vy, ph, pl);
                *(uint32_t*)&Ohi[rowoff + c] = ph;
                *(uint32_t*)&Olo[rowoff + c] = pl;
            }
        }
    }
}

// ---------------------------------------------------------------------------
extern "C" void kernel_launch(void* const* d_in, const int* in_sizes, int n_in,
                              void* d_out, int out_size) {
    const float* x  = (const float*)d_in[0];
    const float* Wq = (const float*)d_in[1];
    const float* Wk = (const float*)d_in[2];
    const float* Wv = (const float*)d_in[3];
    const float* Wo = (const float*)d_in[4];
    float* out = (float*)d_out;

    bf16 *qh, *ql, *kh, *kl, *vh, *vl, *ahi, *alo, *wqh, *wql, *woh, *wol;
    cudaGetSymbolAddress((void**)&qh, g_qhi);
    cudaGetSymbolAddress((void**)&ql, g_qlo);
    cudaGetSymbolAddress((void**)&kh, g_khi);
    cudaGetSymbolAddress((void**)&kl, g_klo);
    cudaGetSymbolAddress((void**)&vh, g_vhi);
    cudaGetSymbolAddress((void**)&vl, g_vlo);
    cudaGetSymbolAddress((void**)&ahi, g_ahi);
    cudaGetSymbolAddress((void**)&alo, g_alo);
    cudaGetSymbolAddress((void**)&wqh, g_wqkv_hi);
    cudaGetSymbolAddress((void**)&wql, g_wqkv_lo);
    cudaGetSymbolAddress((void**)&woh, g_wo_hi);
    cudaGetSymbolAddress((void**)&wol, g_wo_lo);

    cudaFuncSetAttribute(gemm_hmma<0>, cudaFuncAttributeMaxDynamicSharedMemorySize, SM_GEMM);
    cudaFuncSetAttribute(gemm_hmma<1>, cudaFuncAttributeMaxDynamicSharedMemorySize, SM_GEMM);
    cudaFuncSetAttribute(attn_tc, cudaFuncAttributeMaxDynamicSharedMemorySize, SM_ATTN);

    convsplit<<<8192, 256>>>(x, ahi, alo);
    // 0.125 * log2(e): scores land in base-2 domain for exp2f softmax
    transpose_split<<<dim3(32, 32), 256>>>(Wq, wqh, wql, 0, 0.18033688f);
    transpose_split<<<dim3(32, 32), 256>>>(Wk, wqh, wql, 1024, 1.0f);
    transpose_split<<<dim3(32, 32), 256>>>(Wv, wqh, wql, 2048, 1.0f);
    transpose_split<<<dim3(32, 32), 256>>>(Wo, woh, wol, 0, 1.0f);

    gemm_hmma<0><<<dim3(24, 128), 256, SM_GEMM>>>(ahi, alo, wqh, wql, nullptr,
                                                  qh, kh, vh, ql, kl, vl);

    attn_tc<<<dim3(NB, HH, BB), 128, SM_ATTN>>>(qh, ql, kh, kl, vh, vl, ahi, alo);

    gemm_hmma<1><<<dim3(8, 128), 256, SM_GEMM>>>(ahi, alo, woh, wol, out,
                                                 nullptr, nullptr, nullptr,
                                                 nullptr, nullptr, nullptr);
}

// round 17
// speedup vs baseline: 1.5544x; 1.0054x over previous
#include <cuda_runtime.h>
#include <cuda_bf16.h>
#include <cstdint>

// Problem constants
#define BB 2
#define SS 8192
#define DD 1024
#define HH 16
#define DK 64
#define WW 128
#define NB (SS / 128)

typedef __nv_bfloat16 bf16;

// ---------------------------------------------------------------------------
// Scratch (device globals)
// ---------------------------------------------------------------------------
__device__ bf16 g_qhi[(size_t)BB * HH * SS * DK];
__device__ bf16 g_qlo[(size_t)BB * HH * SS * DK];
__device__ bf16 g_khi[(size_t)BB * HH * SS * DK];
__device__ bf16 g_klo[(size_t)BB * HH * SS * DK];
__device__ bf16 g_vhi[(size_t)BB * HH * SS * DK];
__device__ bf16 g_vlo[(size_t)BB * HH * SS * DK];
__device__ bf16 g_ahi[(size_t)16384 * 1024];
__device__ bf16 g_alo[(size_t)16384 * 1024];
__device__ bf16 g_wqkv_hi[(size_t)3072 * 1024];
__device__ bf16 g_wqkv_lo[(size_t)3072 * 1024];
__device__ bf16 g_wo_hi[(size_t)1024 * 1024];
__device__ bf16 g_wo_lo[(size_t)1024 * 1024];

// ---------------------------------------------------------------------------
// Helpers
// ---------------------------------------------------------------------------
__device__ __forceinline__ uint32_t smem_u32(const void* p) {
    uint32_t a;
    asm("{ .reg .u64 t; cvta.to.shared.u64 t, %1; cvt.u32.u64 %0, t; }"
        : "=r"(a) : "l"(p));
    return a;
}
__device__ __forceinline__ void cpa16(uint32_t s, const void* g) {
    asm volatile("cp.async.cg.shared.global [%0], [%1], 16;" :: "r"(s), "l"(g));
}
__device__ __forceinline__ void ldx4(uint32_t* r, uint32_t addr) {
    asm volatile("ldmatrix.sync.aligned.m8n8.x4.shared.b16 {%0,%1,%2,%3}, [%4];"
                 : "=r"(r[0]), "=r"(r[1]), "=r"(r[2]), "=r"(r[3]) : "r"(addr));
}
__device__ __forceinline__ void ldx4t(uint32_t* r, uint32_t addr) {
    asm volatile("ldmatrix.sync.aligned.m8n8.x4.trans.shared.b16 {%0,%1,%2,%3}, [%4];"
                 : "=r"(r[0]), "=r"(r[1]), "=r"(r[2]), "=r"(r[3]) : "r"(addr));
}
__device__ __forceinline__ void mma16816(float* c, const uint32_t* a,
                                         const uint32_t* b) {
    asm volatile(
        "mma.sync.aligned.m16n8k16.row.col.f32.bf16.bf16.f32 "
        "{%0,%1,%2,%3}, {%4,%5,%6,%7}, {%8,%9}, {%0,%1,%2,%3};"
        : "+f"(c[0]), "+f"(c[1]), "+f"(c[2]), "+f"(c[3])
        : "r"(a[0]), "r"(a[1]), "r"(a[2]), "r"(a[3]), "r"(b[0]), "r"(b[1]));
}
__device__ __forceinline__ uint32_t packbf2(bf16 a, bf16 b) {
    __nv_bfloat162 t;
    t.x = a; t.y = b;
    return *reinterpret_cast<uint32_t*>(&t);
}
__device__ __forceinline__ void split2(float a, float b, uint32_t& hi, uint32_t& lo) {
    bf16 ha = __float2bfloat16(a), hb = __float2bfloat16(b);
    bf16 la = __float2bfloat16(a - __bfloat162float(ha));
    bf16 lb = __float2bfloat16(b - __bfloat162float(hb));
    hi = packbf2(ha, hb);
    lo = packbf2(la, lb);
}

// ---------------------------------------------------------------------------
// Elementwise fp32 -> bf16 hi/lo split (for x)
// ---------------------------------------------------------------------------
__global__ __launch_bounds__(256)
void convsplit(const float* __restrict__ in, bf16* __restrict__ hi,
               bf16* __restrict__ lo) {
    size_t i = ((size_t)blockIdx.x * 256 + threadIdx.x) * 8;
    float4 a = *(const float4*)(in + i);
    float4 b = *(const float4*)(in + i + 4);
    float v[8] = {a.x, a.y, a.z, a.w, b.x, b.y, b.z, b.w};
    bf16 h[8], l[8];
#pragma unroll
    for (int j = 0; j < 8; j++) {
        h[j] = __float2bfloat16(v[j]);
        l[j] = __float2bfloat16(v[j] - __bfloat162float(h[j]));
    }
    *(uint4*)(hi + i) = *reinterpret_cast<uint4*>(h);
    *(uint4*)(lo + i) = *reinterpret_cast<uint4*>(l);
}

// ---------------------------------------------------------------------------
// Fused weight transpose + split: all 4 weights in one launch.
// grid (32, 32, 4); z=0..2 -> Wq/Wk/Wv into wqkv (rowoff z*1024), z=3 -> Wo.
// Wq carries 0.125 * log2(e) so scores land in base-2 domain (exp2f softmax).
// ---------------------------------------------------------------------------
__global__ __launch_bounds__(256)
void transpose_split_all(const float* __restrict__ Wq, const float* __restrict__ Wk,
                         const float* __restrict__ Wv, const float* __restrict__ Wo,
                         bf16* __restrict__ Tqkv_hi, bf16* __restrict__ Tqkv_lo,
                         bf16* __restrict__ To_hi, bf16* __restrict__ To_lo) {
    __shared__ float s[32][33];
    const int z = blockIdx.z;
    const float* W = (z == 0) ? Wq : (z == 1) ? Wk : (z == 2) ? Wv : Wo;
    bf16* Thi = (z == 3) ? To_hi : Tqkv_hi;
    bf16* Tlo = (z == 3) ? To_lo : Tqkv_lo;
    const int rowoff = (z == 3) ? 0 : z * 1024;
    const float scale = (z == 0) ? 0.18033688f : 1.0f;

    int tx = threadIdx.x & 31, ty = threadIdx.x >> 5;
    int n0 = blockIdx.x * 32, k0 = blockIdx.y * 32;
#pragma unroll
    for (int i = 0; i < 4; i++)
        s[ty + i * 8][tx] = W[(size_t)(k0 + ty + i * 8) * 1024 + n0 + tx];
    __syncthreads();
#pragma unroll
    for (int i = 0; i < 4; i++) {
        float v = s[tx][ty + i * 8] * scale;
        bf16 h = __float2bfloat16(v);
        size_t o = (size_t)(rowoff + n0 + ty + i * 8) * 1024 + k0 + tx;
        Thi[o] = h;
        Tlo[o] = __float2bfloat16(v - __bfloat162float(h));
    }
}

// ---------------------------------------------------------------------------
// HMMA bf16x3 GEMM — frozen R4 structure (2-stage, 80KB smem).
// MODE 0: out -> Q/K/V bf16 hi/lo [B,H,S,64]; MODE 1: fp32 [M,1024].
// ---------------------------------------------------------------------------
#define STGB 40960
#define SM_GEMM (2 * STGB)

template <int MODE>
__global__ __launch_bounds__(256)
void gemm_hmma(const bf16* __restrict__ Ahi, const bf16* __restrict__ Alo,
               const bf16* __restrict__ Bhi, const bf16* __restrict__ Blo,
               float* __restrict__ oF,
               bf16* __restrict__ qh, bf16* __restrict__ kh, bf16* __restrict__ vh,
               bf16* __restrict__ ql, bf16* __restrict__ kl, bf16* __restrict__ vl) {
    extern __shared__ char smc[];
    const uint32_t sb = smem_u32(smc);
    const int tid = threadIdx.x;
    const int wid = tid >> 5, lane = tid & 31;
    const int wm = wid >> 2, wn = wid & 3;
    const int m_base = wm * 64, n_base = wn * 32;
    const int bm = blockIdx.y * 128;
    const int bn = blockIdx.x * 128;

    float acc[4][4][4];
#pragma unroll
    for (int i = 0; i < 4; i++)
#pragma unroll
        for (int j = 0; j < 4; j++)
#pragma unroll
            for (int r = 0; r < 4; r++) acc[i][j][r] = 0.f;

    const uint32_t a_off = (uint32_t)(m_base + (lane & 15)) * 80 + (lane >> 4) * 16;
    const uint32_t b_off = (uint32_t)(n_base + ((lane >> 4) << 3) + (lane & 7)) * 80 +
                           ((lane >> 3) & 1) * 16;

    auto load_stage = [&](int s) {
        uint32_t ba = sb + (s & 1) * STGB;
        int k0 = s * 32;
#pragma unroll
        for (int it = 0; it < 2; it++) {
            int idx = tid + it * 256;
            int r = idx >> 2, c = idx & 3;
            uint32_t so = (uint32_t)r * 80 + c * 16;
            size_t goA = (size_t)(bm + r) * 1024 + k0 + c * 8;
            size_t goB = (size_t)(bn + r) * 1024 + k0 + c * 8;
            cpa16(ba + so, Ahi + goA);
            cpa16(ba + 10240 + so, Alo + goA);
            cpa16(ba + 20480 + so, Bhi + goB);
            cpa16(ba + 30720 + so, Blo + goB);
        }
        asm volatile("cp.async.commit_group;" ::: "memory");
    };

    load_stage(0);
    for (int s = 0; s < 32; s++) {
        if (s + 1 < 32) {
            load_stage(s + 1);
            asm volatile("cp.async.wait_group 1;" ::: "memory");
        } else {
            asm volatile("cp.async.wait_group 0;" ::: "memory");
        }
        __syncthreads();

        const uint32_t ba = sb + (s & 1) * STGB;
#pragma unroll
        for (int kk = 0; kk < 2; kk++) {
            const uint32_t kb = kk * 32;
            uint32_t ah[4][4], al[4][4], bh[4][2], bl[4][2];
#pragma unroll
            for (int mt = 0; mt < 4; mt++) {
                ldx4(ah[mt], ba + a_off + (uint32_t)mt * 16 * 80 + kb);
                ldx4(al[mt], ba + 10240 + a_off + (uint32_t)mt * 16 * 80 + kb);
            }
#pragma unroll
            for (int np = 0; np < 2; np++) {
                uint32_t t[4];
                ldx4(t, ba + 20480 + b_off + (uint32_t)np * 16 * 80 + kb);
                bh[np * 2][0] = t[0]; bh[np * 2][1] = t[1];
                bh[np * 2 + 1][0] = t[2]; bh[np * 2 + 1][1] = t[3];
                ldx4(t, ba + 30720 + b_off + (uint32_t)np * 16 * 80 + kb);
                bl[np * 2][0] = t[0]; bl[np * 2][1] = t[1];
                bl[np * 2 + 1][0] = t[2]; bl[np * 2 + 1][1] = t[3];
            }
#pragma unroll
            for (int mt = 0; mt < 4; mt++)
#pragma unroll
                for (int nt = 0; nt < 4; nt++) {
                    mma16816(acc[mt][nt], ah[mt], bh[nt]);
                    mma16816(acc[mt][nt], ah[mt], bl[nt]);
                    mma16816(acc[mt][nt], al[mt], bh[nt]);
                }
        }
        __syncthreads();
    }

#pragma unroll
    for (int mt = 0; mt < 4; mt++) {
#pragma unroll
        for (int half = 0; half < 2; half++) {
            int m = bm + m_base + mt * 16 + (lane >> 2) + half * 8;
#pragma unroll
            for (int nt = 0; nt < 4; nt++) {
                int c = n_base + nt * 8 + (lane & 3) * 2;
                float vx = acc[mt][nt][half * 2], vy = acc[mt][nt][half * 2 + 1];
                if (MODE == 0) {
                    int gcol = (bn & 1023) + c;
                    int matid = bn >> 10;
                    bf16* oh = (matid == 0) ? qh : (matid == 1) ? kh : vh;
                    bf16* ol = (matid == 0) ? ql : (matid == 1) ? kl : vl;
                    int h = gcol >> 6, d = gcol & 63;
                    int b = m >> 13, si = m & 8191;
                    size_t off = ((size_t)(b * HH + h) * SS + si) * 64 + d;
                    uint32_t ph, pl;
                    split2(vx, vy, ph, pl);
                    *(uint32_t*)&oh[off] = ph;
                    *(uint32_t*)&ol[off] = pl;
                } else {
                    *(float2*)&oF[(size_t)m * 1024 + bn + c] = make_float2(vx, vy);
                }
            }
        }
    }
}

// ---------------------------------------------------------------------------
// Banded attention on HMMA, bf16x3. 128 threads = 4 warps x 32 query rows.
// K double-buffered; V load overlaps h2=0 QK+softmax.
// Mask geometry (band |i-j| <= 128):
//   kb==n: fully in-band (lean path everywhere).
//   kb==n-1: h2=0 partial for active warps 0-1; h2=1 partial ONLY for w>=2.
//   kb==n+1: h2=1 partial for active warps 2-3; h2=0 partial ONLY for w<2.
// ---------------------------------------------------------------------------
#define AP 144
#define ATB 18432
#define SM_ATTN (6 * ATB)

__global__ __launch_bounds__(128)
void attn_tc(const bf16* __restrict__ Qhi, const bf16* __restrict__ Qlo,
             const bf16* __restrict__ Khi, const bf16* __restrict__ Klo,
             const bf16* __restrict__ Vhi, const bf16* __restrict__ Vlo,
             bf16* __restrict__ Ohi, bf16* __restrict__ Olo) {
    extern __shared__ char smc[];
    const uint32_t sb = smem_u32(smc);
    const int n = blockIdx.x, h = blockIdx.y, b = blockIdx.z;
    const int tid = threadIdx.x, w = tid >> 5, lane = tid & 31;
    const size_t head = (size_t)(b * HH + h) * SS * DK;
    const int qrow0 = n * 128;

    const uint32_t VB = sb + 4 * ATB;

    // ---- Stage Q through the V buffers, consume into registers ----
#pragma unroll
    for (int it = 0; it < 8; it++) {
        int idx = tid + it * 128;
        int r = idx >> 3, c = idx & 7;
        uint32_t so = (uint32_t)r * AP + c * 16;
        size_t go = head + (size_t)(qrow0 + r) * 64 + c * 8;
        cpa16(VB + so, Qhi + go);
        cpa16(VB + ATB + so, Qlo + go);
    }
    asm volatile("cp.async.commit_group;\n\tcp.async.wait_group 0;" ::: "memory");
    __syncthreads();

    uint32_t qfh[2][4][4], qfl[2][4][4];
    const uint32_t a_off = (uint32_t)(w * 32 + (lane & 15)) * AP + (lane >> 4) * 16;
#pragma unroll
    for (int mt = 0; mt < 2; mt++)
#pragma unroll
        for (int kt = 0; kt < 4; kt++) {
            ldx4(qfh[mt][kt], VB + a_off + (uint32_t)mt * 16 * AP + kt * 32);
            ldx4(qfl[mt][kt], VB + ATB + a_off + (uint32_t)mt * 16 * AP + kt * 32);
        }
    __syncthreads();   // Q consumed; V buffer free for overwrite

    auto load_K = [&](int kb, int buf) {
        const uint32_t KB = sb + buf * 2 * ATB;
        const int j0k = kb * 128;
#pragma unroll
        for (int it = 0; it < 8; it++) {
            int idx = tid + it * 128;
            int r = idx >> 3, c = idx & 7;
            uint32_t so = (uint32_t)r * AP + c * 16;
            size_t go = head + (size_t)(j0k + r) * 64 + c * 8;
            cpa16(KB + so, Khi + go);
            cpa16(KB + ATB + so, Klo + go);
        }
        asm volatile("cp.async.commit_group;" ::: "memory");
    };
    auto load_V = [&](int kb) {
        const int j0k = kb * 128;
#pragma unroll
        for (int it = 0; it < 8; it++) {
            int idx = tid + it * 128;
            int r = idx >> 3, c = idx & 7;
            uint32_t so = (uint32_t)r * AP + c * 16;
            size_t go = head + (size_t)(j0k + r) * 64 + c * 8;
            cpa16(VB + so, Vhi + go);
            cpa16(VB + ATB + so, Vlo + go);
        }
        asm volatile("cp.async.commit_group;" ::: "memory");
    };

    float o[2][8][4];
#pragma unroll
    for (int i = 0; i < 2; i++)
#pragma unroll
        for (int j = 0; j < 8; j++)
#pragma unroll
            for (int r = 0; r < 4; r++) o[i][j][r] = 0.f;
    float mrow[4] = {-1e30f, -1e30f, -1e30f, -1e30f};
    float lrow[4] = {0.f, 0.f, 0.f, 0.f};

    const uint32_t kb_off = (uint32_t)(((lane >> 4) << 3) + (lane & 7)) * AP +
                            ((lane >> 3) & 1) * 16;

    const int kb_first = (n == 0) ? 0 : n - 1;
    const int kb_last = (n == NB - 1) ? n : n + 1;

    load_K(kb_first, 0);   // prologue prefetch

    int kcur = 0;
    for (int kb = kb_first; kb <= kb_last; kb++, kcur ^= 1) {
        load_V(kb);
        if (kb < kb_last) {
            load_K(kb + 1, kcur ^ 1);
        } else {
            // empty group keeps the wait-count invariant without wasted traffic
            asm volatile("cp.async.commit_group;" ::: "memory");
        }
        asm volatile("cp.async.wait_group 2;" ::: "memory");   // K(kb) ready
        __syncthreads();

        const int j0k = kb * 128;
        const uint32_t KB = sb + kcur * 2 * ATB;

        for (int h2 = 0; h2 < 2; h2++) {
            const bool act = !((kb == n - 1 && h2 == 0 && w >= 2) ||
                               (kb == n + 1 && h2 == 1 && w < 2));
            // Corrected band-cut geometry (per warp):
            const bool needmask =
                (kb == n - 1) ? (h2 == 0 || w >= 2)
                : (kb == n + 1) ? (h2 == 1 || w < 2)
                : false;
            const int jbase = h2 * 64;
            uint32_t pfh[2][4][4], pfl[2][4][4];

            if (act) {
                // ---- scores S = Q K^T ----
                float sc[2][8][4];
#pragma unroll
                for (int i = 0; i < 2; i++)
#pragma unroll
                    for (int j = 0; j < 8; j++)
#pragma unroll
                        for (int r = 0; r < 4; r++) sc[i][j][r] = 0.f;

#pragma unroll
                for (int kt = 0; kt < 4; kt++) {
#pragma unroll
                    for (int np = 0; np < 4; np++) {
                        uint32_t addr = kb_off + (uint32_t)(jbase + np * 16) * AP + kt * 32;
                        uint32_t th[4], tl[4];
                        ldx4(th, KB + addr);
                        ldx4(tl, KB + ATB + addr);
                        uint32_t bh0[2] = {th[0], th[1]}, bh1[2] = {th[2], th[3]};
                        uint32_t bl0[2] = {tl[0], tl[1]}, bl1[2] = {tl[2], tl[3]};
#pragma unroll
                        for (int mt = 0; mt < 2; mt++) {
                            mma16816(sc[mt][np * 2], qfh[mt][kt], bh0);
                            mma16816(sc[mt][np * 2], qfh[mt][kt], bl0);
                            mma16816(sc[mt][np * 2], qfl[mt][kt], bh0);
                            mma16816(sc[mt][np * 2 + 1], qfh[mt][kt], bh1);
                            mma16816(sc[mt][np * 2 + 1], qfh[mt][kt], bl1);
                            mma16816(sc[mt][np * 2 + 1], qfl[mt][kt], bh1);
                        }
                    }
                }

                // ---- online softmax (mask only where the band cuts) ----
                const int colbase = j0k + jbase + (lane & 3) * 2;
#pragma unroll
                for (int mt = 0; mt < 2; mt++) {
#pragma unroll
                    for (int hf = 0; hf < 2; hf++) {
                        const int i = qrow0 + w * 32 + mt * 16 + (lane >> 2) + hf * 8;
                        const int slot = mt * 2 + hf;
                        float mx = -1e30f;
                        if (needmask) {
#pragma unroll
                            for (int nt = 0; nt < 8; nt++) {
#pragma unroll
                                for (int e = 0; e < 2; e++) {
                                    int j = colbase + nt * 8 + e;
                                    int d = j - i;
                                    float s = sc[mt][nt][hf * 2 + e];
                                    s = (d >= -WW && d <= WW) ? s : -1e30f;
                                    sc[mt][nt][hf * 2 + e] = s;
                                    mx = fmaxf(mx, s);
                                }
                            }
                        } else {
#pragma unroll
                            for (int nt = 0; nt < 8; nt++) {
#pragma unroll
                                for (int e = 0; e < 2; e++)
                                    mx = fmaxf(mx, sc[mt][nt][hf * 2 + e]);
                            }
                        }
                        mx = fmaxf(mx, __shfl_xor_sync(0xffffffffu, mx, 1));
                        mx = fmaxf(mx, __shfl_xor_sync(0xffffffffu, mx, 2));
                        float mnew = fmaxf(mrow[slot], mx);
                        float corr = exp2f(mrow[slot] - mnew);
                        mrow[slot] = mnew;
                        float psum = 0.f;
                        if (needmask) {
#pragma unroll
                            for (int nt = 0; nt < 8; nt++) {
#pragma unroll
                                for (int e = 0; e < 2; e++) {
                                    float s = sc[mt][nt][hf * 2 + e];
                                    float p = (s < -1e29f) ? 0.f : exp2f(s - mnew);
                                    sc[mt][nt][hf * 2 + e] = p;
                                    psum += p;
                                }
                            }
                        } else {
#pragma unroll
                            for (int nt = 0; nt < 8; nt++) {
#pragma unroll
                                for (int e = 0; e < 2; e++) {
                                    float p = exp2f(sc[mt][nt][hf * 2 + e] - mnew);
                                    sc[mt][nt][hf * 2 + e] = p;
                                    psum += p;
                                }
                            }
                        }
                        psum += __shfl_xor_sync(0xffffffffu, psum, 1);
                        psum += __shfl_xor_sync(0xffffffffu, psum, 2);
                        lrow[slot] = lrow[slot] * corr + psum;
#pragma unroll
                        for (int nt = 0; nt < 8; nt++) {
                            o[mt][nt][hf * 2] *= corr;
                            o[mt][nt][hf * 2 + 1] *= corr;
                        }
                    }
                }

                // ---- P -> bf16 hi/lo A-frags ----
#pragma unroll
                for (int mt = 0; mt < 2; mt++)
#pragma unroll
                    for (int kt = 0; kt < 4; kt++) {
                        split2(sc[mt][2 * kt][0], sc[mt][2 * kt][1],
                               pfh[mt][kt][0], pfl[mt][kt][0]);
                        split2(sc[mt][2 * kt][2], sc[mt][2 * kt][3],
                               pfh[mt][kt][1], pfl[mt][kt][1]);
                        split2(sc[mt][2 * kt + 1][0], sc[mt][2 * kt + 1][1],
                               pfh[mt][kt][2], pfl[mt][kt][2]);
                        split2(sc[mt][2 * kt + 1][2], sc[mt][2 * kt + 1][3],
                               pfh[mt][kt][3], pfl[mt][kt][3]);
                    }
            }

            if (h2 == 0) {
                // V load was overlapped with QK(h2=0) + softmax; now required.
                asm volatile("cp.async.wait_group 1;" ::: "memory");
                __syncthreads();
            }

            if (act) {
                // ---- O += P V ----
#pragma unroll
                for (int kt = 0; kt < 4; kt++) {
                    const int k0 = jbase + kt * 16;
#pragma unroll
                    for (int dp = 0; dp < 4; dp++) {
                        uint32_t vaddr =
                            (uint32_t)(k0 + (lane & 7) + ((lane >> 3) & 1) * 8) * AP +
                            (uint32_t)(dp * 16 + (lane >> 4) * 8) * 2;
                        uint32_t th[4], tl[4];
                        ldx4t(th, VB + vaddr);
                        ldx4t(tl, VB + ATB + vaddr);
                        uint32_t bh0[2] = {th[0], th[1]}, bh1[2] = {th[2], th[3]};
                        uint32_t bl0[2] = {tl[0], tl[1]}, bl1[2] = {tl[2], tl[3]};
#pragma unroll
                        for (int mt = 0; mt < 2; mt++) {
                            mma16816(o[mt][dp * 2], pfh[mt][kt], bh0);
                            mma16816(o[mt][dp * 2], pfl[mt][kt], bh0);
                            mma16816(o[mt][dp * 2], pfh[mt][kt], bl0);
                            mma16816(o[mt][dp * 2 + 1], pfh[mt][kt], bh1);
                            mma16816(o[mt][dp * 2 + 1], pfl[mt][kt], bh1);
                            mma16816(o[mt][dp * 2 + 1], pfh[mt][kt], bl1);
                        }
                    }
                }
            }
        }
        __syncthreads();   // V/K consumed before next iteration overwrites
    }

#pragma unroll
    for (int mt = 0; mt < 2; mt++) {
#pragma unroll
        for (int hf = 0; hf < 2; hf++) {
            const int slot = mt * 2 + hf;
            const float inv = 1.f / lrow[slot];
            const int i = qrow0 + w * 32 + mt * 16 + (lane >> 2) + hf * 8;
            const size_t rowoff = ((size_t)b * SS + i) * 1024 + h * 64;
#pragma unroll
            for (int nt = 0; nt < 8; nt++) {
                int c = nt * 8 + (lane & 3) * 2;
                float vx = o[mt][nt][hf * 2] * inv;
                float vy = o[mt][nt][hf * 2 + 1] * inv;
                uint32_t ph, pl;
                split2(vx, vy, ph, pl);
                *(uint32_t*)&Ohi[rowoff + c] = ph;
                *(uint32_t*)&Olo[rowoff + c] = pl;
            }
        }
    }
}

// ---------------------------------------------------------------------------
extern "C" void kernel_launch(void* const* d_in, const int* in_sizes, int n_in,
                              void* d_out, int out_size) {
    const float* x  = (const float*)d_in[0];
    const float* Wq = (const float*)d_in[1];
    const float* Wk = (const float*)d_in[2];
    const float* Wv = (const float*)d_in[3];
    const float* Wo = (const float*)d_in[4];
    float* out = (float*)d_out;

    bf16 *qh, *ql, *kh, *kl, *vh, *vl, *ahi, *alo, *wqh, *wql, *woh, *wol;
    cudaGetSymbolAddress((void**)&qh, g_qhi);
    cudaGetSymbolAddress((void**)&ql, g_qlo);
    cudaGetSymbolAddress((void**)&kh, g_khi);
    cudaGetSymbolAddress((void**)&kl, g_klo);
    cudaGetSymbolAddress((void**)&vh, g_vhi);
    cudaGetSymbolAddress((void**)&vl, g_vlo);
    cudaGetSymbolAddress((void**)&ahi, g_ahi);
    cudaGetSymbolAddress((void**)&alo, g_alo);
    cudaGetSymbolAddress((void**)&wqh, g_wqkv_hi);
    cudaGetSymbolAddress((void**)&wql, g_wqkv_lo);
    cudaGetSymbolAddress((void**)&woh, g_wo_hi);
    cudaGetSymbolAddress((void**)&wol, g_wo_lo);

    cudaFuncSetAttribute(gemm_hmma<0>, cudaFuncAttributeMaxDynamicSharedMemorySize, SM_GEMM);
    cudaFuncSetAttribute(gemm_hmma<1>, cudaFuncAttributeMaxDynamicSharedMemorySize, SM_GEMM);
    cudaFuncSetAttribute(attn_tc, cudaFuncAttributeMaxDynamicSharedMemorySize, SM_ATTN);

    convsplit<<<8192, 256>>>(x, ahi, alo);
    transpose_split_all<<<dim3(32, 32, 4), 256>>>(Wq, Wk, Wv, Wo, wqh, wql, woh, wol);

    gemm_hmma<0><<<dim3(24, 128), 256, SM_GEMM>>>(ahi, alo, wqh, wql, nullptr,
                                                  qh, kh, vh, ql, kl, vl);

    attn_tc<<<dim3(NB, HH, BB), 128, SM_ATTN>>>(qh, ql, kh, kl, vh, vl, ahi, alo);

    gemm_hmma<1><<<dim3(8, 128), 256, SM_GEMM>>>(ahi, alo, woh, wol, out,
                                                 nullptr, nullptr, nullptr,
                                                 nullptr, nullptr, nullptr);
}